// round 14
// baseline (speedup 1.0000x reference)
#include <cuda_runtime.h>
#include <stdint.h>
#include <float.h>

#define BB 2
#define NN 16384
#define MM 4096
#define CC 32
#define DD 64
#define HH 32
#define KK 16
#define KKP 20   // padded k-stride for combT
#define EPSV 1e-5f
#define NQ (BB*MM)   // 8192

// ---------------- scratch ----------------
__device__ float4 g_xyz4[BB*NN];              // padded xyz; .w = |p|^2
__device__ float  g_featsT[BB*NN*CC];
__device__ int    g_knn[NQ*KK];
__device__ float  g_comb[(size_t)NQ*KK*DD];
__device__ float  g_sc1[NQ*DD];
__device__ float  g_sc2[NQ*DD];
__device__ float  g_outp[NQ*DD];
__device__ float  g_stats[512];
__device__ float  g_bn[512];

// ---------------- K0: zero stats, write xyz_ds + sample_idx ----------------
__global__ void k_init(const float* __restrict__ xyz, const int* __restrict__ sidx,
                       float* __restrict__ out) {
    int t = blockIdx.x * 256 + threadIdx.x;
    if (t < 512) g_stats[t] = 0.f;
    if (t < NQ) {
        int b = t >> 12;
        int n = sidx[t];
        const float* p = xyz + ((size_t)b * NN + n) * 3;
        out[t * 3 + 0] = p[0];
        out[t * 3 + 1] = p[1];
        out[t * 3 + 2] = p[2];
        out[24576 + 524288 + t] = (float)n;
    }
}

// ---------------- K0a: pad xyz into float4 with w = |p|^2 ----------------
__global__ void k_prep(const float* __restrict__ xyz) {
    int t = blockIdx.x * 256 + threadIdx.x;   // over B*N = 32768
    if (t < BB * NN) {
        float x = xyz[3 * t], y = xyz[3 * t + 1], z = xyz[3 * t + 2];
        float w = fmaf(x, x, fmaf(y, y, z * z));
        g_xyz4[t] = make_float4(x, y, z, w);
    }
}

// ---------------- K0b: transpose feats [B,C,N] -> [B,N,C] (4 rows/thread) ----------------
__global__ void k_transpose(const float* __restrict__ feats) {
    __shared__ float tile[32][33];
    int b = blockIdx.y;
    int n0 = blockIdx.x * 32;
    int tx = threadIdx.x, ty = threadIdx.y;     // (32, 8)
#pragma unroll
    for (int i = 0; i < 4; i++) {
        int c = ty * 4 + i;
        tile[c][tx] = feats[((size_t)b * CC + c) * NN + n0 + tx];
    }
    __syncthreads();
#pragma unroll
    for (int i = 0; i < 4; i++) {
        int n = ty * 4 + i;
        g_featsT[((size_t)b * NN + n0 + n) * CC + tx] = tile[tx][n];
    }
}

// warp-shared sorted top-16 insert (lanes 0..15 ascending; lane 15 = threshold)
__device__ __forceinline__ void knn_insert(float nd, int ni, int lane,
                                           float& bk, int& bi, float& w) {
    float upk = __shfl_up_sync(0xffffffffu, bk, 1);
    int   upi = __shfl_up_sync(0xffffffffu, bi, 1);
    unsigned gt = __ballot_sync(0xffffffffu, (lane < KK) && (bk > nd));
    int fg = __ffs(gt) - 1;
    if ((lane < KK) && bk > nd) {
        if (lane == fg) { bk = nd;  bi = ni; }
        else            { bk = upk; bi = upi; }
    }
    w = __shfl_sync(0xffffffffu, bk, KK - 1);
}

// ---------------- K1: KNN — 2 queries/warp, 4-group ballots, register prefetch ----------------
#define TS 2048
__global__ __launch_bounds__(256) void k_knn(const int* __restrict__ sidx) {
    __shared__ float4 tile[TS];
    int warp = threadIdx.x >> 5, lane = threadIdx.x & 31;
    int qbase = (blockIdx.x * 8 + warp) * 2;     // grid=512 -> queries 0..8191
    int b = qbase >> 12;
    const float4* xb = g_xyz4 + (size_t)b * NN;

    float4 q0p = xb[sidx[qbase]];
    float4 q1p = xb[sidx[qbase + 1]];
    float ax0 = -2.f * q0p.x, ay0 = -2.f * q0p.y, az0 = -2.f * q0p.z;
    float ax1 = -2.f * q1p.x, ay1 = -2.f * q1p.y, az1 = -2.f * q1p.z;

    float bk0 = FLT_MAX, bk1 = FLT_MAX;
    int   bi0 = 0,       bi1 = 0;
    float w0 = FLT_MAX,  w1 = FLT_MAX;

    for (int t0 = 0; t0 < NN; t0 += TS) {
        __syncthreads();
        for (int i = threadIdx.x; i < TS; i += 256)
            tile[i] = xb[t0 + i];
        __syncthreads();
        // prime prefetch registers with group 0
        float4 pa = tile[lane];
        float4 pb = tile[32 + lane];
        float4 pc = tile[64 + lane];
        float4 pd = tile[96 + lane];
        for (int i0 = 0; i0 < TS; i0 += 128) {
            float4 ca = pa, cb4 = pb, cc = pc, cd = pd;
            if (i0 + 128 < TS) {      // prefetch next group while computing this one
                pa = tile[i0 + 128 + lane];
                pb = tile[i0 + 160 + lane];
                pc = tile[i0 + 192 + lane];
                pd = tile[i0 + 224 + lane];
            }
            float d00 = fmaf(ca.x,  ax0, fmaf(ca.y,  ay0, fmaf(ca.z,  az0, ca.w)));
            float d01 = fmaf(cb4.x, ax0, fmaf(cb4.y, ay0, fmaf(cb4.z, az0, cb4.w)));
            float d02 = fmaf(cc.x,  ax0, fmaf(cc.y,  ay0, fmaf(cc.z,  az0, cc.w)));
            float d03 = fmaf(cd.x,  ax0, fmaf(cd.y,  ay0, fmaf(cd.z,  az0, cd.w)));
            float d10 = fmaf(ca.x,  ax1, fmaf(ca.y,  ay1, fmaf(ca.z,  az1, ca.w)));
            float d11 = fmaf(cb4.x, ax1, fmaf(cb4.y, ay1, fmaf(cb4.z, az1, cb4.w)));
            float d12 = fmaf(cc.x,  ax1, fmaf(cc.y,  ay1, fmaf(cc.z,  az1, cc.w)));
            float d13 = fmaf(cd.x,  ax1, fmaf(cd.y,  ay1, fmaf(cd.z,  az1, cd.w)));
            float m0 = fminf(fminf(d00, d01), fminf(d02, d03));
            float m1 = fminf(fminf(d10, d11), fminf(d12, d13));
            unsigned ball0 = __ballot_sync(0xffffffffu, m0 < w0);
            while (ball0) {
                int src = __ffs(ball0) - 1;
                ball0 &= ball0 - 1;
                float nd;
                nd = __shfl_sync(0xffffffffu, d00, src);
                if (nd < w0) knn_insert(nd, t0 + i0 + src,      lane, bk0, bi0, w0);
                nd = __shfl_sync(0xffffffffu, d01, src);
                if (nd < w0) knn_insert(nd, t0 + i0 + 32 + src, lane, bk0, bi0, w0);
                nd = __shfl_sync(0xffffffffu, d02, src);
                if (nd < w0) knn_insert(nd, t0 + i0 + 64 + src, lane, bk0, bi0, w0);
                nd = __shfl_sync(0xffffffffu, d03, src);
                if (nd < w0) knn_insert(nd, t0 + i0 + 96 + src, lane, bk0, bi0, w0);
            }
            unsigned ball1 = __ballot_sync(0xffffffffu, m1 < w1);
            while (ball1) {
                int src = __ffs(ball1) - 1;
                ball1 &= ball1 - 1;
                float nd;
                nd = __shfl_sync(0xffffffffu, d10, src);
                if (nd < w1) knn_insert(nd, t0 + i0 + src,      lane, bk1, bi1, w1);
                nd = __shfl_sync(0xffffffffu, d11, src);
                if (nd < w1) knn_insert(nd, t0 + i0 + 32 + src, lane, bk1, bi1, w1);
                nd = __shfl_sync(0xffffffffu, d12, src);
                if (nd < w1) knn_insert(nd, t0 + i0 + 64 + src, lane, bk1, bi1, w1);
                nd = __shfl_sync(0xffffffffu, d13, src);
                if (nd < w1) knn_insert(nd, t0 + i0 + 96 + src, lane, bk1, bi1, w1);
            }
        }
    }
    if (lane < KK) {
        g_knn[qbase * KK + lane] = bi0;
        g_knn[(qbase + 1) * KK + lane] = bi1;
    }
}

// ---------------- K2: gather + pos/feat linear + shortcuts + stats ----------------
__global__ __launch_bounds__(256) void k_stage2(
    const float* __restrict__ xyz, const int* __restrict__ sidx,
    const float* __restrict__ Wp, const float* __restrict__ bp,
    const float* __restrict__ Wf, const float* __restrict__ bf,
    const float* __restrict__ Wsc1, const float* __restrict__ Wsc2) {
    __shared__ __align__(16) float nf[8][KK][CC];
    __shared__ float posf[8][KK][10];
    __shared__ float mf[8][CC];
    __shared__ float cfs[8][CC];
    __shared__ int   nidx[8][KK];
    __shared__ float acc[384];
    __shared__ float swf[CC][HH];
    __shared__ float ssc1[CC][DD];
    __shared__ float ssc2[CC][DD];

    int tid = threadIdx.x;
    for (int i = tid; i < 384; i += 256) acc[i] = 0.f;
    for (int i = tid; i < CC * HH; i += 256) ((float*)swf)[i] = Wf[i];
    for (int i = tid; i < CC * DD; i += 256) {
        ((float*)ssc1)[i] = Wsc1[i];
        ((float*)ssc2)[i] = Wsc2[i];
    }
    __syncthreads();

    int warp = tid >> 5, lane = tid & 31;
    int q = blockIdx.x * 8 + warp;
    int b = q >> 12;
    const float* ftb = g_featsT + (size_t)b * NN * CC;
    const float4* xb = g_xyz4 + (size_t)b * NN;
    int sn = sidx[q];
    float4 qp = xb[sn];
    float qx = qp.x, qy = qp.y, qz = qp.z;

    if (lane < KK) nidx[warp][lane] = g_knn[q * KK + lane];
    __syncwarp();
#pragma unroll
    for (int k = 0; k < KK; k++) {
        int n = nidx[warp][k];
        nf[warp][k][lane] = ftb[n * CC + lane];
    }
    if (lane < KK) {
        int n = nidx[warp][lane];
        float4 pp = xb[n];
        float rx = qx - pp.x, ry = qy - pp.y, rz = qz - pp.z;
        float dist = sqrtf(rx * rx + ry * ry + rz * rz);
        float* pf = posf[warp][lane];
        pf[0] = qx; pf[1] = qy; pf[2] = qz;
        pf[3] = pp.x; pf[4] = pp.y; pf[5] = pp.z;
        pf[6] = rx; pf[7] = ry; pf[8] = rz; pf[9] = dist;
    }
    cfs[warp][lane] = ftb[sn * CC + lane];
    __syncwarp();

    float* cb = g_comb + (size_t)q * KK * DD;

    {
        float wp[10];
#pragma unroll
        for (int j = 0; j < 10; j++) wp[j] = Wp[j * HH + lane];
        float bias = bp[lane];
        float s1 = 0.f, s2 = 0.f;
        for (int k = 0; k < KK; k++) {
            float v0 = 0.f, v1 = 0.f;
#pragma unroll
            for (int j = 0; j < 5; j++) {
                v0 = fmaf(posf[warp][k][j],     wp[j],     v0);
                v1 = fmaf(posf[warp][k][j + 5], wp[j + 5], v1);
            }
            float v = bias + (v0 + v1);
            cb[k * DD + 32 + lane] = v;
            s1 += v; s2 = fmaf(v, v, s2);
        }
        atomicAdd(&acc[0 + lane], s1);
        atomicAdd(&acc[32 + lane], s2);
    }
    {
        float v[KK];
        float bias = bf[lane];
#pragma unroll
        for (int k = 0; k < KK; k++) v[k] = bias;
#pragma unroll
        for (int ch = 0; ch < 4; ch++) {
            float wq0 = swf[ch * 8 + 0][lane], wq1 = swf[ch * 8 + 1][lane];
            float wq2 = swf[ch * 8 + 2][lane], wq3 = swf[ch * 8 + 3][lane];
            float wq4 = swf[ch * 8 + 4][lane], wq5 = swf[ch * 8 + 5][lane];
            float wq6 = swf[ch * 8 + 6][lane], wq7 = swf[ch * 8 + 7][lane];
#pragma unroll
            for (int k = 0; k < KK; k++) {
                const float4* n4 = reinterpret_cast<const float4*>(nf[warp][k]);
                float4 na = n4[ch * 2], nb = n4[ch * 2 + 1];
                float t0 = fmaf(na.x, wq0, fmaf(na.y, wq1, fmaf(na.z, wq2, na.w * wq3)));
                float t1 = fmaf(nb.x, wq4, fmaf(nb.y, wq5, fmaf(nb.z, wq6, nb.w * wq7)));
                v[k] += t0 + t1;
            }
        }
        float s1 = 0.f, s2 = 0.f;
#pragma unroll
        for (int k = 0; k < KK; k++) {
            cb[k * DD + lane] = v[k];
            s1 += v[k]; s2 = fmaf(v[k], v[k], s2);
        }
        atomicAdd(&acc[64 + lane], s1);
        atomicAdd(&acc[96 + lane], s2);
    }
    {
        float mv = 0.f;
#pragma unroll
        for (int k = 0; k < KK; k++) mv += nf[warp][k][lane];
        mf[warp][lane] = mv * (1.f / 16.f);
    }
    __syncwarp();
    {
        float a1a = 0.f, a1b = 0.f, a1c = 0.f, a1d = 0.f;
        float a2a = 0.f, a2b = 0.f, a2c = 0.f, a2d = 0.f;
#pragma unroll
        for (int c = 0; c < CC; c += 2) {
            float m0 = mf[warp][c],  m1 = mf[warp][c + 1];
            float f0 = cfs[warp][c], f1 = cfs[warp][c + 1];
            a1a = fmaf(m0, ssc1[c][lane],          a1a);
            a1b = fmaf(m1, ssc1[c + 1][lane],      a1b);
            a1c = fmaf(m0, ssc1[c][lane + 32],     a1c);
            a1d = fmaf(m1, ssc1[c + 1][lane + 32], a1d);
            a2a = fmaf(f0, ssc2[c][lane],          a2a);
            a2b = fmaf(f1, ssc2[c + 1][lane],      a2b);
            a2c = fmaf(f0, ssc2[c][lane + 32],     a2c);
            a2d = fmaf(f1, ssc2[c + 1][lane + 32], a2d);
        }
        float a1lo = a1a + a1b, a1hi = a1c + a1d;
        float a2lo = a2a + a2b, a2hi = a2c + a2d;
        g_sc1[q * DD + lane] = a1lo;       g_sc1[q * DD + lane + 32] = a1hi;
        g_sc2[q * DD + lane] = a2lo;       g_sc2[q * DD + lane + 32] = a2hi;
        atomicAdd(&acc[128 + lane], a1lo);        atomicAdd(&acc[128 + lane + 32], a1hi);
        atomicAdd(&acc[192 + lane], a1lo * a1lo); atomicAdd(&acc[192 + lane + 32], a1hi * a1hi);
        atomicAdd(&acc[256 + lane], a2lo);        atomicAdd(&acc[256 + lane + 32], a2hi);
        atomicAdd(&acc[320 + lane], a2lo * a2lo); atomicAdd(&acc[320 + lane + 32], a2hi * a2hi);
    }
    __syncthreads();
    for (int i = tid; i < 384; i += 256) atomicAdd(&g_stats[i], acc[i]);
}

// ---------------- K3: finalize BN coeffs ----------------
__global__ void k_fstats1(const float* __restrict__ gpos, const float* __restrict__ bepos,
                          const float* __restrict__ gfeat, const float* __restrict__ befeat,
                          const float* __restrict__ gsc1, const float* __restrict__ besc1,
                          const float* __restrict__ gsc2, const float* __restrict__ besc2) {
    int d = threadIdx.x;
    float n1 = (float)((size_t)NQ * KK);
    float s1, s2, g, be;
    if (d < 32) { s1 = g_stats[64 + d]; s2 = g_stats[96 + d]; g = gfeat[d]; be = befeat[d]; }
    else { int h = d - 32; s1 = g_stats[h]; s2 = g_stats[32 + h]; g = gpos[h]; be = bepos[h]; }
    float mu = s1 / n1, var = s2 / n1 - mu * mu;
    float a = g * rsqrtf(var + EPSV);
    g_bn[d] = a; g_bn[64 + d] = be - mu * a;

    float n2 = (float)NQ;
    s1 = g_stats[128 + d]; s2 = g_stats[192 + d];
    mu = s1 / n2; var = s2 / n2 - mu * mu;
    a = gsc1[d] * rsqrtf(var + EPSV);
    g_bn[128 + d] = a; g_bn[192 + d] = besc1[d] - mu * a;

    s1 = g_stats[256 + d]; s2 = g_stats[320 + d];
    mu = s1 / n2; var = s2 / n2 - mu * mu;
    a = gsc2[d] * rsqrtf(var + EPSV);
    g_bn[256 + d] = a; g_bn[320 + d] = besc2[d] - mu * a;
}

// ---------------- K4: attention + pooling + W_out + stats ----------------
__global__ __launch_bounds__(256) void k_attn(const float* __restrict__ Ws,
                                              const float* __restrict__ Wo) {
    __shared__ __align__(16) float combT[8][DD][KKP];
    __shared__ float pool[8][DD];
    __shared__ float acc[128];
    int tid = threadIdx.x;
    if (tid < 128) acc[tid] = 0.f;
    __syncthreads();

    int warp = tid >> 5, lane = tid & 31;
    int q = blockIdx.x * 8 + warp;
    float a0 = g_bn[lane],      b0 = g_bn[64 + lane];
    float a1 = g_bn[lane + 32], b1 = g_bn[64 + lane + 32];
    const float* cp = g_comb + (size_t)q * KK * DD;

#pragma unroll
    for (int k = 0; k < KK; k++) {
        float v0 = fmaxf(fmaf(a0, cp[k * DD + lane],      b0), 0.f);
        float v1 = fmaxf(fmaf(a1, cp[k * DD + lane + 32], b1), 0.f);
        combT[warp][lane][k]      = v0;
        combT[warp][lane + 32][k] = v1;
    }
    __syncwarp();

    float s0[KK], s1v[KK];
#pragma unroll
    for (int k = 0; k < KK; k++) { s0[k] = 0.f; s1v[k] = 0.f; }
    for (int dp = 0; dp < DD; dp++) {
        const float4* row = reinterpret_cast<const float4*>(combT[warp][dp]);
        float4 A0 = row[0], A1 = row[1], A2 = row[2], A3 = row[3];
        float w0 = Ws[dp * DD + lane];
        float w1 = Ws[dp * DD + lane + 32];
        float av[KK] = {A0.x, A0.y, A0.z, A0.w, A1.x, A1.y, A1.z, A1.w,
                        A2.x, A2.y, A2.z, A2.w, A3.x, A3.y, A3.z, A3.w};
#pragma unroll
        for (int k = 0; k < KK; k++) {
            s0[k]  = fmaf(av[k], w0, s0[k]);
            s1v[k] = fmaf(av[k], w1, s1v[k]);
        }
    }
    float p0 = 0.f, p1 = 0.f;
    {
        float mx = s0[0];
#pragma unroll
        for (int k = 1; k < KK; k++) mx = fmaxf(mx, s0[k]);
        float sum = 0.f;
#pragma unroll
        for (int k = 0; k < KK; k++) { float e = __expf(s0[k] - mx); s0[k] = e; sum += e; }
        float inv = 1.f / sum;
        const float4* r0 = reinterpret_cast<const float4*>(combT[warp][lane]);
        float4 C0 = r0[0], C1 = r0[1], C2 = r0[2], C3 = r0[3];
        float cv[KK] = {C0.x, C0.y, C0.z, C0.w, C1.x, C1.y, C1.z, C1.w,
                        C2.x, C2.y, C2.z, C2.w, C3.x, C3.y, C3.z, C3.w};
#pragma unroll
        for (int k = 0; k < KK; k++) p0 = fmaf(s0[k] * inv, cv[k], p0);
    }
    {
        float mx = s1v[0];
#pragma unroll
        for (int k = 1; k < KK; k++) mx = fmaxf(mx, s1v[k]);
        float sum = 0.f;
#pragma unroll
        for (int k = 0; k < KK; k++) { float e = __expf(s1v[k] - mx); s1v[k] = e; sum += e; }
        float inv = 1.f / sum;
        const float4* r1 = reinterpret_cast<const float4*>(combT[warp][lane + 32]);
        float4 C0 = r1[0], C1 = r1[1], C2 = r1[2], C3 = r1[3];
        float cv[KK] = {C0.x, C0.y, C0.z, C0.w, C1.x, C1.y, C1.z, C1.w,
                        C2.x, C2.y, C2.z, C2.w, C3.x, C3.y, C3.z, C3.w};
#pragma unroll
        for (int k = 0; k < KK; k++) p1 = fmaf(s1v[k] * inv, cv[k], p1);
    }
    pool[warp][lane] = p0;
    pool[warp][lane + 32] = p1;
    __syncwarp();

    float o0 = 0.f, o1 = 0.f;
    for (int dp = 0; dp < DD; dp++) {
        float pv = pool[warp][dp];
        o0 = fmaf(pv, Wo[dp * DD + lane],      o0);
        o1 = fmaf(pv, Wo[dp * DD + lane + 32], o1);
    }
    g_outp[q * DD + lane] = o0;
    g_outp[q * DD + lane + 32] = o1;
    atomicAdd(&acc[lane], o0);
    atomicAdd(&acc[lane + 32], o1);
    atomicAdd(&acc[64 + lane], o0 * o0);
    atomicAdd(&acc[64 + lane + 32], o1 * o1);
    __syncthreads();
    if (tid < 128) atomicAdd(&g_stats[384 + tid], acc[tid]);
}

// ---------------- K5a: finalize out BN ----------------
__global__ void k_fout(const float* __restrict__ gout, const float* __restrict__ beout) {
    int d = threadIdx.x;
    float n = (float)NQ;
    float s1 = g_stats[384 + d], s2 = g_stats[448 + d];
    float mu = s1 / n, var = s2 / n - mu * mu;
    float a = gout[d] * rsqrtf(var + EPSV);
    g_bn[384 + d] = a; g_bn[448 + d] = beout[d] - mu * a;
}

// ---------------- K5: fused epilogue (coalesced), y transposed [B,D,M] ----------------
__global__ __launch_bounds__(256) void k_final(float* __restrict__ out) {
    __shared__ float sm[32][65];
    int blk = blockIdx.x;
    int b = blk >> 7;
    int m0 = (blk & 127) * 32;
    int warp = threadIdx.x >> 5, lane = threadIdx.x & 31;
#pragma unroll
    for (int i = 0; i < 4; i++) {
        int r = warp * 4 + i;
        int q = b * MM + m0 + r;
#pragma unroll
        for (int h = 0; h < 2; h++) {
            int d = lane + 32 * h;
            float o  = fmaxf(fmaf(g_bn[384 + d], g_outp[q * DD + d], g_bn[448 + d]), 0.f);
            float v1 = fmaf(g_bn[128 + d], g_sc1[q * DD + d], g_bn[192 + d]);
            float v2 = fmaf(g_bn[256 + d], g_sc2[q * DD + d], g_bn[320 + d]);
            sm[r][d] = fmaxf(o + v1 + v2, 0.f);
        }
    }
    __syncthreads();
#pragma unroll
    for (int i = 0; i < 8; i++) {
        int d = warp * 8 + i;
        out[24576 + ((size_t)(b * DD + d)) * MM + m0 + lane] = sm[lane][d];
    }
}

// ---------------- launch ----------------
extern "C" void kernel_launch(void* const* d_in, const int* in_sizes, int n_in,
                              void* d_out, int out_size) {
    const float* xyz    = (const float*)d_in[0];
    const float* feats  = (const float*)d_in[1];
    const int*   sidx   = (const int*)  d_in[2];
    const float* Wpos   = (const float*)d_in[3];
    const float* bpos   = (const float*)d_in[4];
    const float* gpos   = (const float*)d_in[5];
    const float* bepos  = (const float*)d_in[6];
    const float* Wfeat  = (const float*)d_in[7];
    const float* bfeat  = (const float*)d_in[8];
    const float* gfeat  = (const float*)d_in[9];
    const float* befeat = (const float*)d_in[10];
    const float* Wscore = (const float*)d_in[11];
    const float* Wout   = (const float*)d_in[12];
    const float* gout   = (const float*)d_in[13];
    const float* beout  = (const float*)d_in[14];
    const float* Wsc1   = (const float*)d_in[15];
    const float* gsc1   = (const float*)d_in[16];
    const float* besc1  = (const float*)d_in[17];
    const float* Wsc2   = (const float*)d_in[18];
    const float* gsc2   = (const float*)d_in[19];
    const float* besc2  = (const float*)d_in[20];
    float* out = (float*)d_out;

    k_init<<<32, 256>>>(xyz, sidx, out);
    k_prep<<<(BB * NN) / 256, 256>>>(xyz);
    dim3 tb(32, 8);
    k_transpose<<<dim3(NN / 32, BB), tb>>>(feats);
    k_knn<<<NQ / 16, 256>>>(sidx);
    k_stage2<<<NQ / 8, 256>>>(xyz, sidx, Wpos, bpos, Wfeat, bfeat, Wsc1, Wsc2);
    k_fstats1<<<1, 64>>>(gpos, bepos, gfeat, befeat, gsc1, besc1, gsc2, besc2);
    k_attn<<<NQ / 8, 256>>>(Wscore, Wout);
    k_fout<<<1, 64>>>(gout, beout);
    k_final<<<256, 256>>>(out);
}

// round 15
// speedup vs baseline: 1.0770x; 1.0770x over previous
#include <cuda_runtime.h>
#include <stdint.h>
#include <float.h>

#define BB 2
#define NN 16384
#define MM 4096
#define CC 32
#define DD 64
#define HH 32
#define KK 16
#define KKP 20   // padded k-stride for combT
#define EPSV 1e-5f
#define NQ (BB*MM)   // 8192

// ---------------- scratch ----------------
__device__ float4 g_xyz4[BB*NN];              // padded xyz; .w = |p|^2
__device__ float  g_featsT[BB*NN*CC];
__device__ int    g_knn[NQ*KK];
__device__ float  g_comb[(size_t)NQ*KK*DD];
__device__ float  g_sc1[NQ*DD];
__device__ float  g_sc2[NQ*DD];
__device__ float  g_outp[NQ*DD];
__device__ float  g_stats[512];
__device__ float  g_bn[512];

// ---------------- K0: zero stats, write xyz_ds + sample_idx ----------------
__global__ void k_init(const float* __restrict__ xyz, const int* __restrict__ sidx,
                       float* __restrict__ out) {
    int t = blockIdx.x * 256 + threadIdx.x;
    if (t < 512) g_stats[t] = 0.f;
    if (t < NQ) {
        int b = t >> 12;
        int n = sidx[t];
        const float* p = xyz + ((size_t)b * NN + n) * 3;
        out[t * 3 + 0] = p[0];
        out[t * 3 + 1] = p[1];
        out[t * 3 + 2] = p[2];
        out[24576 + 524288 + t] = (float)n;
    }
}

// ---------------- K0a: pad xyz into float4 with w = |p|^2 ----------------
__global__ void k_prep(const float* __restrict__ xyz) {
    int t = blockIdx.x * 256 + threadIdx.x;   // over B*N = 32768
    if (t < BB * NN) {
        float x = xyz[3 * t], y = xyz[3 * t + 1], z = xyz[3 * t + 2];
        float w = fmaf(x, x, fmaf(y, y, z * z));
        g_xyz4[t] = make_float4(x, y, z, w);
    }
}

// ---------------- K0b: transpose feats [B,C,N] -> [B,N,C] (4 rows/thread) ----------------
__global__ void k_transpose(const float* __restrict__ feats) {
    __shared__ float tile[32][33];
    int b = blockIdx.y;
    int n0 = blockIdx.x * 32;
    int tx = threadIdx.x, ty = threadIdx.y;     // (32, 8)
#pragma unroll
    for (int i = 0; i < 4; i++) {
        int c = ty * 4 + i;
        tile[c][tx] = feats[((size_t)b * CC + c) * NN + n0 + tx];
    }
    __syncthreads();
#pragma unroll
    for (int i = 0; i < 4; i++) {
        int n = ty * 4 + i;
        g_featsT[((size_t)b * NN + n0 + n) * CC + tx] = tile[tx][n];
    }
}

// warp-shared sorted top-16 insert (lanes 0..15 ascending; lane 15 = threshold)
__device__ __forceinline__ void knn_insert(float nd, int ni, int lane,
                                           float& bk, int& bi, float& w) {
    float upk = __shfl_up_sync(0xffffffffu, bk, 1);
    int   upi = __shfl_up_sync(0xffffffffu, bi, 1);
    unsigned gt = __ballot_sync(0xffffffffu, (lane < KK) && (bk > nd));
    int fg = __ffs(gt) - 1;
    if ((lane < KK) && bk > nd) {
        if (lane == fg) { bk = nd;  bi = ni; }
        else            { bk = upk; bi = upi; }
    }
    w = __shfl_sync(0xffffffffu, bk, KK - 1);
}

// ---------------- K1: KNN — 2 queries/warp, 4-group batched ballots (R10/R13 best) ----------------
#define TS 2048
__global__ __launch_bounds__(256) void k_knn(const int* __restrict__ sidx) {
    __shared__ float4 tile[TS];
    int warp = threadIdx.x >> 5, lane = threadIdx.x & 31;
    int qbase = (blockIdx.x * 8 + warp) * 2;     // grid=512 -> queries 0..8191
    int b = qbase >> 12;
    const float4* xb = g_xyz4 + (size_t)b * NN;

    float4 q0p = xb[sidx[qbase]];
    float4 q1p = xb[sidx[qbase + 1]];
    float ax0 = -2.f * q0p.x, ay0 = -2.f * q0p.y, az0 = -2.f * q0p.z;
    float ax1 = -2.f * q1p.x, ay1 = -2.f * q1p.y, az1 = -2.f * q1p.z;

    float bk0 = FLT_MAX, bk1 = FLT_MAX;
    int   bi0 = 0,       bi1 = 0;
    float w0 = FLT_MAX,  w1 = FLT_MAX;

    for (int t0 = 0; t0 < NN; t0 += TS) {
        __syncthreads();
        for (int i = threadIdx.x; i < TS; i += 256)
            tile[i] = xb[t0 + i];
        __syncthreads();
        for (int i0 = 0; i0 < TS; i0 += 128) {
            float4 pa = tile[i0 + lane];
            float4 pb = tile[i0 + 32 + lane];
            float4 pc = tile[i0 + 64 + lane];
            float4 pd = tile[i0 + 96 + lane];
            float d00 = fmaf(pa.x, ax0, fmaf(pa.y, ay0, fmaf(pa.z, az0, pa.w)));
            float d01 = fmaf(pb.x, ax0, fmaf(pb.y, ay0, fmaf(pb.z, az0, pb.w)));
            float d02 = fmaf(pc.x, ax0, fmaf(pc.y, ay0, fmaf(pc.z, az0, pc.w)));
            float d03 = fmaf(pd.x, ax0, fmaf(pd.y, ay0, fmaf(pd.z, az0, pd.w)));
            float d10 = fmaf(pa.x, ax1, fmaf(pa.y, ay1, fmaf(pa.z, az1, pa.w)));
            float d11 = fmaf(pb.x, ax1, fmaf(pb.y, ay1, fmaf(pb.z, az1, pb.w)));
            float d12 = fmaf(pc.x, ax1, fmaf(pc.y, ay1, fmaf(pc.z, az1, pc.w)));
            float d13 = fmaf(pd.x, ax1, fmaf(pd.y, ay1, fmaf(pd.z, az1, pd.w)));
            float m0 = fminf(fminf(d00, d01), fminf(d02, d03));
            float m1 = fminf(fminf(d10, d11), fminf(d12, d13));
            unsigned ball0 = __ballot_sync(0xffffffffu, m0 < w0);
            while (ball0) {
                int src = __ffs(ball0) - 1;
                ball0 &= ball0 - 1;
                float nd;
                nd = __shfl_sync(0xffffffffu, d00, src);
                if (nd < w0) knn_insert(nd, t0 + i0 + src,      lane, bk0, bi0, w0);
                nd = __shfl_sync(0xffffffffu, d01, src);
                if (nd < w0) knn_insert(nd, t0 + i0 + 32 + src, lane, bk0, bi0, w0);
                nd = __shfl_sync(0xffffffffu, d02, src);
                if (nd < w0) knn_insert(nd, t0 + i0 + 64 + src, lane, bk0, bi0, w0);
                nd = __shfl_sync(0xffffffffu, d03, src);
                if (nd < w0) knn_insert(nd, t0 + i0 + 96 + src, lane, bk0, bi0, w0);
            }
            unsigned ball1 = __ballot_sync(0xffffffffu, m1 < w1);
            while (ball1) {
                int src = __ffs(ball1) - 1;
                ball1 &= ball1 - 1;
                float nd;
                nd = __shfl_sync(0xffffffffu, d10, src);
                if (nd < w1) knn_insert(nd, t0 + i0 + src,      lane, bk1, bi1, w1);
                nd = __shfl_sync(0xffffffffu, d11, src);
                if (nd < w1) knn_insert(nd, t0 + i0 + 32 + src, lane, bk1, bi1, w1);
                nd = __shfl_sync(0xffffffffu, d12, src);
                if (nd < w1) knn_insert(nd, t0 + i0 + 64 + src, lane, bk1, bi1, w1);
                nd = __shfl_sync(0xffffffffu, d13, src);
                if (nd < w1) knn_insert(nd, t0 + i0 + 96 + src, lane, bk1, bi1, w1);
            }
        }
    }
    if (lane < KK) {
        g_knn[qbase * KK + lane] = bi0;
        g_knn[(qbase + 1) * KK + lane] = bi1;
    }
}

// ---------------- K2: gather + pos/feat linear + shortcuts + stats ----------------
__global__ __launch_bounds__(256) void k_stage2(
    const float* __restrict__ xyz, const int* __restrict__ sidx,
    const float* __restrict__ Wp, const float* __restrict__ bp,
    const float* __restrict__ Wf, const float* __restrict__ bf,
    const float* __restrict__ Wsc1, const float* __restrict__ Wsc2) {
    __shared__ __align__(16) float nf[8][KK][CC];
    __shared__ float posf[8][KK][10];
    __shared__ float mf[8][CC];
    __shared__ float cfs[8][CC];
    __shared__ int   nidx[8][KK];
    __shared__ float acc[384];
    __shared__ float swf[CC][HH];
    __shared__ float ssc1[CC][DD];
    __shared__ float ssc2[CC][DD];

    int tid = threadIdx.x;
    for (int i = tid; i < 384; i += 256) acc[i] = 0.f;
    for (int i = tid; i < CC * HH; i += 256) ((float*)swf)[i] = Wf[i];
    for (int i = tid; i < CC * DD; i += 256) {
        ((float*)ssc1)[i] = Wsc1[i];
        ((float*)ssc2)[i] = Wsc2[i];
    }
    __syncthreads();

    int warp = tid >> 5, lane = tid & 31;
    int q = blockIdx.x * 8 + warp;
    int b = q >> 12;
    const float* ftb = g_featsT + (size_t)b * NN * CC;
    const float4* xb = g_xyz4 + (size_t)b * NN;
    int sn = sidx[q];
    float4 qp = xb[sn];
    float qx = qp.x, qy = qp.y, qz = qp.z;

    if (lane < KK) nidx[warp][lane] = g_knn[q * KK + lane];
    __syncwarp();
#pragma unroll
    for (int k = 0; k < KK; k++) {
        int n = nidx[warp][k];
        nf[warp][k][lane] = ftb[n * CC + lane];
    }
    if (lane < KK) {
        int n = nidx[warp][lane];
        float4 pp = xb[n];
        float rx = qx - pp.x, ry = qy - pp.y, rz = qz - pp.z;
        float dist = sqrtf(rx * rx + ry * ry + rz * rz);
        float* pf = posf[warp][lane];
        pf[0] = qx; pf[1] = qy; pf[2] = qz;
        pf[3] = pp.x; pf[4] = pp.y; pf[5] = pp.z;
        pf[6] = rx; pf[7] = ry; pf[8] = rz; pf[9] = dist;
    }
    cfs[warp][lane] = ftb[sn * CC + lane];
    __syncwarp();

    float* cb = g_comb + (size_t)q * KK * DD;

    {
        float wp[10];
#pragma unroll
        for (int j = 0; j < 10; j++) wp[j] = Wp[j * HH + lane];
        float bias = bp[lane];
        float s1 = 0.f, s2 = 0.f;
        for (int k = 0; k < KK; k++) {
            float v0 = 0.f, v1 = 0.f;
#pragma unroll
            for (int j = 0; j < 5; j++) {
                v0 = fmaf(posf[warp][k][j],     wp[j],     v0);
                v1 = fmaf(posf[warp][k][j + 5], wp[j + 5], v1);
            }
            float v = bias + (v0 + v1);
            cb[k * DD + 32 + lane] = v;
            s1 += v; s2 = fmaf(v, v, s2);
        }
        atomicAdd(&acc[0 + lane], s1);
        atomicAdd(&acc[32 + lane], s2);
    }
    {
        float v[KK];
        float bias = bf[lane];
#pragma unroll
        for (int k = 0; k < KK; k++) v[k] = bias;
#pragma unroll
        for (int ch = 0; ch < 4; ch++) {
            float wq0 = swf[ch * 8 + 0][lane], wq1 = swf[ch * 8 + 1][lane];
            float wq2 = swf[ch * 8 + 2][lane], wq3 = swf[ch * 8 + 3][lane];
            float wq4 = swf[ch * 8 + 4][lane], wq5 = swf[ch * 8 + 5][lane];
            float wq6 = swf[ch * 8 + 6][lane], wq7 = swf[ch * 8 + 7][lane];
#pragma unroll
            for (int k = 0; k < KK; k++) {
                const float4* n4 = reinterpret_cast<const float4*>(nf[warp][k]);
                float4 na = n4[ch * 2], nb = n4[ch * 2 + 1];
                float t0 = fmaf(na.x, wq0, fmaf(na.y, wq1, fmaf(na.z, wq2, na.w * wq3)));
                float t1 = fmaf(nb.x, wq4, fmaf(nb.y, wq5, fmaf(nb.z, wq6, nb.w * wq7)));
                v[k] += t0 + t1;
            }
        }
        float s1 = 0.f, s2 = 0.f;
#pragma unroll
        for (int k = 0; k < KK; k++) {
            cb[k * DD + lane] = v[k];
            s1 += v[k]; s2 = fmaf(v[k], v[k], s2);
        }
        atomicAdd(&acc[64 + lane], s1);
        atomicAdd(&acc[96 + lane], s2);
    }
    {
        float mv = 0.f;
#pragma unroll
        for (int k = 0; k < KK; k++) mv += nf[warp][k][lane];
        mf[warp][lane] = mv * (1.f / 16.f);
    }
    __syncwarp();
    {
        float a1a = 0.f, a1b = 0.f, a1c = 0.f, a1d = 0.f;
        float a2a = 0.f, a2b = 0.f, a2c = 0.f, a2d = 0.f;
#pragma unroll
        for (int c = 0; c < CC; c += 2) {
            float m0 = mf[warp][c],  m1 = mf[warp][c + 1];
            float f0 = cfs[warp][c], f1 = cfs[warp][c + 1];
            a1a = fmaf(m0, ssc1[c][lane],          a1a);
            a1b = fmaf(m1, ssc1[c + 1][lane],      a1b);
            a1c = fmaf(m0, ssc1[c][lane + 32],     a1c);
            a1d = fmaf(m1, ssc1[c + 1][lane + 32], a1d);
            a2a = fmaf(f0, ssc2[c][lane],          a2a);
            a2b = fmaf(f1, ssc2[c + 1][lane],      a2b);
            a2c = fmaf(f0, ssc2[c][lane + 32],     a2c);
            a2d = fmaf(f1, ssc2[c + 1][lane + 32], a2d);
        }
        float a1lo = a1a + a1b, a1hi = a1c + a1d;
        float a2lo = a2a + a2b, a2hi = a2c + a2d;
        g_sc1[q * DD + lane] = a1lo;       g_sc1[q * DD + lane + 32] = a1hi;
        g_sc2[q * DD + lane] = a2lo;       g_sc2[q * DD + lane + 32] = a2hi;
        atomicAdd(&acc[128 + lane], a1lo);        atomicAdd(&acc[128 + lane + 32], a1hi);
        atomicAdd(&acc[192 + lane], a1lo * a1lo); atomicAdd(&acc[192 + lane + 32], a1hi * a1hi);
        atomicAdd(&acc[256 + lane], a2lo);        atomicAdd(&acc[256 + lane + 32], a2hi);
        atomicAdd(&acc[320 + lane], a2lo * a2lo); atomicAdd(&acc[320 + lane + 32], a2hi * a2hi);
    }
    __syncthreads();
    for (int i = tid; i < 384; i += 256) atomicAdd(&g_stats[i], acc[i]);
}

// ---------------- K3: finalize BN coeffs ----------------
__global__ void k_fstats1(const float* __restrict__ gpos, const float* __restrict__ bepos,
                          const float* __restrict__ gfeat, const float* __restrict__ befeat,
                          const float* __restrict__ gsc1, const float* __restrict__ besc1,
                          const float* __restrict__ gsc2, const float* __restrict__ besc2) {
    int d = threadIdx.x;
    float n1 = (float)((size_t)NQ * KK);
    float s1, s2, g, be;
    if (d < 32) { s1 = g_stats[64 + d]; s2 = g_stats[96 + d]; g = gfeat[d]; be = befeat[d]; }
    else { int h = d - 32; s1 = g_stats[h]; s2 = g_stats[32 + h]; g = gpos[h]; be = bepos[h]; }
    float mu = s1 / n1, var = s2 / n1 - mu * mu;
    float a = g * rsqrtf(var + EPSV);
    g_bn[d] = a; g_bn[64 + d] = be - mu * a;

    float n2 = (float)NQ;
    s1 = g_stats[128 + d]; s2 = g_stats[192 + d];
    mu = s1 / n2; var = s2 / n2 - mu * mu;
    a = gsc1[d] * rsqrtf(var + EPSV);
    g_bn[128 + d] = a; g_bn[192 + d] = besc1[d] - mu * a;

    s1 = g_stats[256 + d]; s2 = g_stats[320 + d];
    mu = s1 / n2; var = s2 / n2 - mu * mu;
    a = gsc2[d] * rsqrtf(var + EPSV);
    g_bn[256 + d] = a; g_bn[320 + d] = besc2[d] - mu * a;
}

// ---------------- K4: attention + pooling + W_out + stats (FFMA2 score GEMM) ----------------
__device__ __forceinline__ unsigned long long pack2(float lo, float hi) {
    unsigned long long r;
    asm("mov.b64 %0, {%1, %2};" : "=l"(r) : "f"(lo), "f"(hi));
    return r;
}
__device__ __forceinline__ void unpack2(unsigned long long v, float& lo, float& hi) {
    asm("mov.b64 {%0, %1}, %2;" : "=f"(lo), "=f"(hi) : "l"(v));
}
__device__ __forceinline__ void ffma2(unsigned long long& acc, unsigned long long a,
                                      unsigned long long b) {
    asm("fma.rn.f32x2 %0, %1, %2, %0;" : "+l"(acc) : "l"(a), "l"(b));
}

__global__ __launch_bounds__(256) void k_attn(const float* __restrict__ Ws,
                                              const float* __restrict__ Wo) {
    __shared__ __align__(16) float combT[8][DD][KKP];
    __shared__ float pool[8][DD];
    __shared__ float acc[128];
    int tid = threadIdx.x;
    if (tid < 128) acc[tid] = 0.f;
    __syncthreads();

    int warp = tid >> 5, lane = tid & 31;
    int q = blockIdx.x * 8 + warp;
    float a0 = g_bn[lane],      b0 = g_bn[64 + lane];
    float a1 = g_bn[lane + 32], b1 = g_bn[64 + lane + 32];
    const float* cp = g_comb + (size_t)q * KK * DD;

#pragma unroll
    for (int k = 0; k < KK; k++) {
        float v0 = fmaxf(fmaf(a0, cp[k * DD + lane],      b0), 0.f);
        float v1 = fmaxf(fmaf(a1, cp[k * DD + lane + 32], b1), 0.f);
        combT[warp][lane][k]      = v0;
        combT[warp][lane + 32][k] = v1;
    }
    __syncwarp();

    // score GEMM with packed f32x2 accumulators: s0p[j] = (s0[2j], s0[2j+1])
    unsigned long long s0p[8], s1p[8];
#pragma unroll
    for (int j = 0; j < 8; j++) { s0p[j] = 0ull; s1p[j] = 0ull; }
    for (int dp = 0; dp < DD; dp++) {
        const float4* row = reinterpret_cast<const float4*>(combT[warp][dp]);
        float4 A0 = row[0], A1 = row[1], A2 = row[2], A3 = row[3];
        float w0 = Ws[dp * DD + lane];
        float w1 = Ws[dp * DD + lane + 32];
        unsigned long long w00 = pack2(w0, w0);
        unsigned long long w11 = pack2(w1, w1);
        unsigned long long ap[8];
        ap[0] = pack2(A0.x, A0.y); ap[1] = pack2(A0.z, A0.w);
        ap[2] = pack2(A1.x, A1.y); ap[3] = pack2(A1.z, A1.w);
        ap[4] = pack2(A2.x, A2.y); ap[5] = pack2(A2.z, A2.w);
        ap[6] = pack2(A3.x, A3.y); ap[7] = pack2(A3.z, A3.w);
#pragma unroll
        for (int j = 0; j < 8; j++) {
            ffma2(s0p[j], ap[j], w00);
            ffma2(s1p[j], ap[j], w11);
        }
    }
    float s0[KK], s1v[KK];
#pragma unroll
    for (int j = 0; j < 8; j++) {
        unpack2(s0p[j], s0[2 * j], s0[2 * j + 1]);
        unpack2(s1p[j], s1v[2 * j], s1v[2 * j + 1]);
    }

    float p0 = 0.f, p1 = 0.f;
    {
        float mx = s0[0];
#pragma unroll
        for (int k = 1; k < KK; k++) mx = fmaxf(mx, s0[k]);
        float sum = 0.f;
#pragma unroll
        for (int k = 0; k < KK; k++) { float e = __expf(s0[k] - mx); s0[k] = e; sum += e; }
        float inv = 1.f / sum;
        const float4* r0 = reinterpret_cast<const float4*>(combT[warp][lane]);
        float4 C0 = r0[0], C1 = r0[1], C2 = r0[2], C3 = r0[3];
        float cv[KK] = {C0.x, C0.y, C0.z, C0.w, C1.x, C1.y, C1.z, C1.w,
                        C2.x, C2.y, C2.z, C2.w, C3.x, C3.y, C3.z, C3.w};
#pragma unroll
        for (int k = 0; k < KK; k++) p0 = fmaf(s0[k] * inv, cv[k], p0);
    }
    {
        float mx = s1v[0];
#pragma unroll
        for (int k = 1; k < KK; k++) mx = fmaxf(mx, s1v[k]);
        float sum = 0.f;
#pragma unroll
        for (int k = 0; k < KK; k++) { float e = __expf(s1v[k] - mx); s1v[k] = e; sum += e; }
        float inv = 1.f / sum;
        const float4* r1 = reinterpret_cast<const float4*>(combT[warp][lane + 32]);
        float4 C0 = r1[0], C1 = r1[1], C2 = r1[2], C3 = r1[3];
        float cv[KK] = {C0.x, C0.y, C0.z, C0.w, C1.x, C1.y, C1.z, C1.w,
                        C2.x, C2.y, C2.z, C2.w, C3.x, C3.y, C3.z, C3.w};
#pragma unroll
        for (int k = 0; k < KK; k++) p1 = fmaf(s1v[k] * inv, cv[k], p1);
    }
    pool[warp][lane] = p0;
    pool[warp][lane + 32] = p1;
    __syncwarp();

    float o0 = 0.f, o1 = 0.f;
    for (int dp = 0; dp < DD; dp++) {
        float pv = pool[warp][dp];
        o0 = fmaf(pv, Wo[dp * DD + lane],      o0);
        o1 = fmaf(pv, Wo[dp * DD + lane + 32], o1);
    }
    g_outp[q * DD + lane] = o0;
    g_outp[q * DD + lane + 32] = o1;
    atomicAdd(&acc[lane], o0);
    atomicAdd(&acc[lane + 32], o1);
    atomicAdd(&acc[64 + lane], o0 * o0);
    atomicAdd(&acc[64 + lane + 32], o1 * o1);
    __syncthreads();
    if (tid < 128) atomicAdd(&g_stats[384 + tid], acc[tid]);
}

// ---------------- K5a: finalize out BN ----------------
__global__ void k_fout(const float* __restrict__ gout, const float* __restrict__ beout) {
    int d = threadIdx.x;
    float n = (float)NQ;
    float s1 = g_stats[384 + d], s2 = g_stats[448 + d];
    float mu = s1 / n, var = s2 / n - mu * mu;
    float a = gout[d] * rsqrtf(var + EPSV);
    g_bn[384 + d] = a; g_bn[448 + d] = beout[d] - mu * a;
}

// ---------------- K5: fused epilogue (coalesced), y transposed [B,D,M] ----------------
__global__ __launch_bounds__(256) void k_final(float* __restrict__ out) {
    __shared__ float sm[32][65];
    int blk = blockIdx.x;
    int b = blk >> 7;
    int m0 = (blk & 127) * 32;
    int warp = threadIdx.x >> 5, lane = threadIdx.x & 31;
#pragma unroll
    for (int i = 0; i < 4; i++) {
        int r = warp * 4 + i;
        int q = b * MM + m0 + r;
#pragma unroll
        for (int h = 0; h < 2; h++) {
            int d = lane + 32 * h;
            float o  = fmaxf(fmaf(g_bn[384 + d], g_outp[q * DD + d], g_bn[448 + d]), 0.f);
            float v1 = fmaf(g_bn[128 + d], g_sc1[q * DD + d], g_bn[192 + d]);
            float v2 = fmaf(g_bn[256 + d], g_sc2[q * DD + d], g_bn[320 + d]);
            sm[r][d] = fmaxf(o + v1 + v2, 0.f);
        }
    }
    __syncthreads();
#pragma unroll
    for (int i = 0; i < 8; i++) {
        int d = warp * 8 + i;
        out[24576 + ((size_t)(b * DD + d)) * MM + m0 + lane] = sm[lane][d];
    }
}

// ---------------- launch ----------------
extern "C" void kernel_launch(void* const* d_in, const int* in_sizes, int n_in,
                              void* d_out, int out_size) {
    const float* xyz    = (const float*)d_in[0];
    const float* feats  = (const float*)d_in[1];
    const int*   sidx   = (const int*)  d_in[2];
    const float* Wpos   = (const float*)d_in[3];
    const float* bpos   = (const float*)d_in[4];
    const float* gpos   = (const float*)d_in[5];
    const float* bepos  = (const float*)d_in[6];
    const float* Wfeat  = (const float*)d_in[7];
    const float* bfeat  = (const float*)d_in[8];
    const float* gfeat  = (const float*)d_in[9];
    const float* befeat = (const float*)d_in[10];
    const float* Wscore = (const float*)d_in[11];
    const float* Wout   = (const float*)d_in[12];
    const float* gout   = (const float*)d_in[13];
    const float* beout  = (const float*)d_in[14];
    const float* Wsc1   = (const float*)d_in[15];
    const float* gsc1   = (const float*)d_in[16];
    const float* besc1  = (const float*)d_in[17];
    const float* Wsc2   = (const float*)d_in[18];
    const float* gsc2   = (const float*)d_in[19];
    const float* besc2  = (const float*)d_in[20];
    float* out = (float*)d_out;

    k_init<<<32, 256>>>(xyz, sidx, out);
    k_prep<<<(BB * NN) / 256, 256>>>(xyz);
    dim3 tb(32, 8);
    k_transpose<<<dim3(NN / 32, BB), tb>>>(feats);
    k_knn<<<NQ / 16, 256>>>(sidx);
    k_stage2<<<NQ / 8, 256>>>(xyz, sidx, Wpos, bpos, Wfeat, bfeat, Wsc1, Wsc2);
    k_fstats1<<<1, 64>>>(gpos, bepos, gfeat, befeat, gsc1, besc1, gsc2, besc2);
    k_attn<<<NQ / 8, 256>>>(Wscore, Wout);
    k_fout<<<1, 64>>>(gout, beout);
    k_final<<<256, 256>>>(out);
}

// round 16
// speedup vs baseline: 1.0852x; 1.0076x over previous
#include <cuda_runtime.h>
#include <stdint.h>
#include <float.h>

#define BB 2
#define NN 16384
#define MM 4096
#define CC 32
#define DD 64
#define HH 32
#define KK 16
#define KKP 20   // padded k-stride for combT
#define EPSV 1e-5f
#define NQ (BB*MM)   // 8192

// ---------------- scratch ----------------
__device__ float4 g_xyz4[BB*NN];              // padded xyz; .w = |p|^2
__device__ float  g_featsT[BB*NN*CC];
__device__ int    g_knn[NQ*KK];
__device__ float  g_comb[(size_t)NQ*KK*DD];
__device__ float  g_sc1[NQ*DD];
__device__ float  g_sc2[NQ*DD];
__device__ float  g_outp[NQ*DD];
__device__ float  g_stats[512];
__device__ float  g_bn[512];

// ---------------- f32x2 helpers ----------------
__device__ __forceinline__ unsigned long long pack2(float lo, float hi) {
    unsigned long long r;
    asm("mov.b64 %0, {%1, %2};" : "=l"(r) : "f"(lo), "f"(hi));
    return r;
}
__device__ __forceinline__ void unpack2(unsigned long long v, float& lo, float& hi) {
    asm("mov.b64 {%0, %1}, %2;" : "=f"(lo), "=f"(hi) : "l"(v));
}
__device__ __forceinline__ void ffma2(unsigned long long& acc, unsigned long long a,
                                      unsigned long long b) {
    asm("fma.rn.f32x2 %0, %1, %2, %0;" : "+l"(acc) : "l"(a), "l"(b));
}

// ---------------- K0: zero stats, write xyz_ds + sample_idx, pad xyz ----------------
__global__ void k_init(const float* __restrict__ xyz, const int* __restrict__ sidx,
                       float* __restrict__ out) {
    int t = blockIdx.x * 256 + threadIdx.x;   // 32768 threads
    if (t < 512) g_stats[t] = 0.f;
    if (t < NQ) {
        int b = t >> 12;
        int n = sidx[t];
        const float* p = xyz + ((size_t)b * NN + n) * 3;
        out[t * 3 + 0] = p[0];
        out[t * 3 + 1] = p[1];
        out[t * 3 + 2] = p[2];
        out[24576 + 524288 + t] = (float)n;
    }
    if (t < BB * NN) {
        float x = xyz[3 * t], y = xyz[3 * t + 1], z = xyz[3 * t + 2];
        float w = fmaf(x, x, fmaf(y, y, z * z));
        g_xyz4[t] = make_float4(x, y, z, w);
    }
}

// ---------------- K0b: transpose feats [B,C,N] -> [B,N,C] (4 rows/thread) ----------------
__global__ void k_transpose(const float* __restrict__ feats) {
    __shared__ float tile[32][33];
    int b = blockIdx.y;
    int n0 = blockIdx.x * 32;
    int tx = threadIdx.x, ty = threadIdx.y;     // (32, 8)
#pragma unroll
    for (int i = 0; i < 4; i++) {
        int c = ty * 4 + i;
        tile[c][tx] = feats[((size_t)b * CC + c) * NN + n0 + tx];
    }
    __syncthreads();
#pragma unroll
    for (int i = 0; i < 4; i++) {
        int n = ty * 4 + i;
        g_featsT[((size_t)b * NN + n0 + n) * CC + tx] = tile[tx][n];
    }
}

// warp-shared sorted top-16 insert (lanes 0..15 ascending; lane 15 = threshold)
__device__ __forceinline__ void knn_insert(float nd, int ni, int lane,
                                           float& bk, int& bi, float& w) {
    float upk = __shfl_up_sync(0xffffffffu, bk, 1);
    int   upi = __shfl_up_sync(0xffffffffu, bi, 1);
    unsigned gt = __ballot_sync(0xffffffffu, (lane < KK) && (bk > nd));
    int fg = __ffs(gt) - 1;
    if ((lane < KK) && bk > nd) {
        if (lane == fg) { bk = nd;  bi = ni; }
        else            { bk = upk; bi = upi; }
    }
    w = __shfl_sync(0xffffffffu, bk, KK - 1);
}

// ---------------- K1: KNN — 2 queries/warp, 4-group batched ballots (measured optimum) ----------------
#define TS 2048
__global__ __launch_bounds__(256) void k_knn(const int* __restrict__ sidx) {
    __shared__ float4 tile[TS];
    int warp = threadIdx.x >> 5, lane = threadIdx.x & 31;
    int qbase = (blockIdx.x * 8 + warp) * 2;     // grid=512 -> queries 0..8191
    int b = qbase >> 12;
    const float4* xb = g_xyz4 + (size_t)b * NN;

    float4 q0p = xb[sidx[qbase]];
    float4 q1p = xb[sidx[qbase + 1]];
    float ax0 = -2.f * q0p.x, ay0 = -2.f * q0p.y, az0 = -2.f * q0p.z;
    float ax1 = -2.f * q1p.x, ay1 = -2.f * q1p.y, az1 = -2.f * q1p.z;

    float bk0 = FLT_MAX, bk1 = FLT_MAX;
    int   bi0 = 0,       bi1 = 0;
    float w0 = FLT_MAX,  w1 = FLT_MAX;

    for (int t0 = 0; t0 < NN; t0 += TS) {
        __syncthreads();
        for (int i = threadIdx.x; i < TS; i += 256)
            tile[i] = xb[t0 + i];
        __syncthreads();
        for (int i0 = 0; i0 < TS; i0 += 128) {
            float4 pa = tile[i0 + lane];
            float4 pb = tile[i0 + 32 + lane];
            float4 pc = tile[i0 + 64 + lane];
            float4 pd = tile[i0 + 96 + lane];
            float d00 = fmaf(pa.x, ax0, fmaf(pa.y, ay0, fmaf(pa.z, az0, pa.w)));
            float d01 = fmaf(pb.x, ax0, fmaf(pb.y, ay0, fmaf(pb.z, az0, pb.w)));
            float d02 = fmaf(pc.x, ax0, fmaf(pc.y, ay0, fmaf(pc.z, az0, pc.w)));
            float d03 = fmaf(pd.x, ax0, fmaf(pd.y, ay0, fmaf(pd.z, az0, pd.w)));
            float d10 = fmaf(pa.x, ax1, fmaf(pa.y, ay1, fmaf(pa.z, az1, pa.w)));
            float d11 = fmaf(pb.x, ax1, fmaf(pb.y, ay1, fmaf(pb.z, az1, pb.w)));
            float d12 = fmaf(pc.x, ax1, fmaf(pc.y, ay1, fmaf(pc.z, az1, pc.w)));
            float d13 = fmaf(pd.x, ax1, fmaf(pd.y, ay1, fmaf(pd.z, az1, pd.w)));
            float m0 = fminf(fminf(d00, d01), fminf(d02, d03));
            float m1 = fminf(fminf(d10, d11), fminf(d12, d13));
            unsigned ball0 = __ballot_sync(0xffffffffu, m0 < w0);
            while (ball0) {
                int src = __ffs(ball0) - 1;
                ball0 &= ball0 - 1;
                float nd;
                nd = __shfl_sync(0xffffffffu, d00, src);
                if (nd < w0) knn_insert(nd, t0 + i0 + src,      lane, bk0, bi0, w0);
                nd = __shfl_sync(0xffffffffu, d01, src);
                if (nd < w0) knn_insert(nd, t0 + i0 + 32 + src, lane, bk0, bi0, w0);
                nd = __shfl_sync(0xffffffffu, d02, src);
                if (nd < w0) knn_insert(nd, t0 + i0 + 64 + src, lane, bk0, bi0, w0);
                nd = __shfl_sync(0xffffffffu, d03, src);
                if (nd < w0) knn_insert(nd, t0 + i0 + 96 + src, lane, bk0, bi0, w0);
            }
            unsigned ball1 = __ballot_sync(0xffffffffu, m1 < w1);
            while (ball1) {
                int src = __ffs(ball1) - 1;
                ball1 &= ball1 - 1;
                float nd;
                nd = __shfl_sync(0xffffffffu, d10, src);
                if (nd < w1) knn_insert(nd, t0 + i0 + src,      lane, bk1, bi1, w1);
                nd = __shfl_sync(0xffffffffu, d11, src);
                if (nd < w1) knn_insert(nd, t0 + i0 + 32 + src, lane, bk1, bi1, w1);
                nd = __shfl_sync(0xffffffffu, d12, src);
                if (nd < w1) knn_insert(nd, t0 + i0 + 64 + src, lane, bk1, bi1, w1);
                nd = __shfl_sync(0xffffffffu, d13, src);
                if (nd < w1) knn_insert(nd, t0 + i0 + 96 + src, lane, bk1, bi1, w1);
            }
        }
    }
    if (lane < KK) {
        g_knn[qbase * KK + lane] = bi0;
        g_knn[(qbase + 1) * KK + lane] = bi1;
    }
}

// ---------------- K2: gather + pos/feat linear + shortcuts + stats (FFMA2) ----------------
__global__ __launch_bounds__(256) void k_stage2(
    const float* __restrict__ xyz, const int* __restrict__ sidx,
    const float* __restrict__ Wp, const float* __restrict__ bp,
    const float* __restrict__ Wf, const float* __restrict__ bf,
    const float* __restrict__ Wsc1, const float* __restrict__ Wsc2) {
    __shared__ __align__(16) float nf[8][KK][CC];
    __shared__ __align__(8) float posf[8][KK][10];
    __shared__ float mf[8][CC];
    __shared__ float cfs[8][CC];
    __shared__ int   nidx[8][KK];
    __shared__ float acc[384];
    __shared__ float swf[CC][HH];                 // Wf [c][h]  4KB
    __shared__ __align__(8) float2 ssc12[CC][DD]; // (Wsc1, Wsc2) interleaved 16KB

    int tid = threadIdx.x;
    for (int i = tid; i < 384; i += 256) acc[i] = 0.f;
    for (int i = tid; i < CC * HH; i += 256) ((float*)swf)[i] = Wf[i];
    for (int i = tid; i < CC * DD; i += 256)
        ((float2*)ssc12)[i] = make_float2(Wsc1[i], Wsc2[i]);
    __syncthreads();

    int warp = tid >> 5, lane = tid & 31;
    int q = blockIdx.x * 8 + warp;
    int b = q >> 12;
    const float* ftb = g_featsT + (size_t)b * NN * CC;
    const float4* xb = g_xyz4 + (size_t)b * NN;
    int sn = sidx[q];
    float4 qp = xb[sn];
    float qx = qp.x, qy = qp.y, qz = qp.z;

    if (lane < KK) nidx[warp][lane] = g_knn[q * KK + lane];
    __syncwarp();
#pragma unroll
    for (int k = 0; k < KK; k++) {
        int n = nidx[warp][k];
        nf[warp][k][lane] = ftb[n * CC + lane];
    }
    if (lane < KK) {
        int n = nidx[warp][lane];
        float4 pp = xb[n];
        float rx = qx - pp.x, ry = qy - pp.y, rz = qz - pp.z;
        float dist = sqrtf(rx * rx + ry * ry + rz * rz);
        float* pf = posf[warp][lane];
        pf[0] = qx; pf[1] = qy; pf[2] = qz;
        pf[3] = pp.x; pf[4] = pp.y; pf[5] = pp.z;
        pf[6] = rx; pf[7] = ry; pf[8] = rz; pf[9] = dist;
    }
    cfs[warp][lane] = ftb[sn * CC + lane];
    __syncwarp();

    float* cb = g_comb + (size_t)q * KK * DD;

    // positional linear: lane = channel h; packed pair accumulation over 10 features
    {
        unsigned long long wpp[5];
#pragma unroll
        for (int j = 0; j < 5; j++)
            wpp[j] = pack2(Wp[(2 * j) * HH + lane], Wp[(2 * j + 1) * HH + lane]);
        float bias = bp[lane];
        float s1 = 0.f, s2 = 0.f;
        for (int k = 0; k < KK; k++) {
            const float2* pf2 = reinterpret_cast<const float2*>(posf[warp][k]);
            unsigned long long a2 = 0ull;
#pragma unroll
            for (int j = 0; j < 5; j++) {
                float2 pp2 = pf2[j];
                ffma2(a2, pack2(pp2.x, pp2.y), wpp[j]);
            }
            float lo, hi; unpack2(a2, lo, hi);
            float v = bias + (lo + hi);
            cb[k * DD + 32 + lane] = v;
            s1 += v; s2 = fmaf(v, v, s2);
        }
        atomicAdd(&acc[0 + lane], s1);
        atomicAdd(&acc[32 + lane], s2);
    }
    // feature linear: packed channel-pair accumulators
    {
        unsigned long long v2[KK];
#pragma unroll
        for (int k = 0; k < KK; k++) v2[k] = 0ull;
#pragma unroll
        for (int ch = 0; ch < 4; ch++) {
            unsigned long long w01 = pack2(swf[ch * 8 + 0][lane], swf[ch * 8 + 1][lane]);
            unsigned long long w23 = pack2(swf[ch * 8 + 2][lane], swf[ch * 8 + 3][lane]);
            unsigned long long w45 = pack2(swf[ch * 8 + 4][lane], swf[ch * 8 + 5][lane]);
            unsigned long long w67 = pack2(swf[ch * 8 + 6][lane], swf[ch * 8 + 7][lane]);
#pragma unroll
            for (int k = 0; k < KK; k++) {
                const float4* n4 = reinterpret_cast<const float4*>(nf[warp][k]);
                float4 na = n4[ch * 2], nb = n4[ch * 2 + 1];
                ffma2(v2[k], pack2(na.x, na.y), w01);
                ffma2(v2[k], pack2(na.z, na.w), w23);
                ffma2(v2[k], pack2(nb.x, nb.y), w45);
                ffma2(v2[k], pack2(nb.z, nb.w), w67);
            }
        }
        float bias = bf[lane];
        float s1 = 0.f, s2 = 0.f;
#pragma unroll
        for (int k = 0; k < KK; k++) {
            float lo, hi; unpack2(v2[k], lo, hi);
            float v = bias + (lo + hi);
            cb[k * DD + lane] = v;
            s1 += v; s2 = fmaf(v, v, s2);
        }
        atomicAdd(&acc[64 + lane], s1);
        atomicAdd(&acc[96 + lane], s2);
    }
    // mean over K (lane = channel c)
    {
        float mv = 0.f;
#pragma unroll
        for (int k = 0; k < KK; k++) mv += nf[warp][k][lane];
        mf[warp][lane] = mv * (1.f / 16.f);
    }
    __syncwarp();
    // shortcuts: packed (a1,a2) accumulation with interleaved weights
    {
        unsigned long long accLo = 0ull, accHi = 0ull;
#pragma unroll
        for (int c = 0; c < CC; c++) {
            unsigned long long mfp = pack2(mf[warp][c], cfs[warp][c]);
            float2 wlo = ssc12[c][lane];
            float2 whi = ssc12[c][lane + 32];
            ffma2(accLo, mfp, pack2(wlo.x, wlo.y));
            ffma2(accHi, mfp, pack2(whi.x, whi.y));
        }
        float a1lo, a2lo, a1hi, a2hi;
        unpack2(accLo, a1lo, a2lo);
        unpack2(accHi, a1hi, a2hi);
        g_sc1[q * DD + lane] = a1lo;       g_sc1[q * DD + lane + 32] = a1hi;
        g_sc2[q * DD + lane] = a2lo;       g_sc2[q * DD + lane + 32] = a2hi;
        atomicAdd(&acc[128 + lane], a1lo);        atomicAdd(&acc[128 + lane + 32], a1hi);
        atomicAdd(&acc[192 + lane], a1lo * a1lo); atomicAdd(&acc[192 + lane + 32], a1hi * a1hi);
        atomicAdd(&acc[256 + lane], a2lo);        atomicAdd(&acc[256 + lane + 32], a2hi);
        atomicAdd(&acc[320 + lane], a2lo * a2lo); atomicAdd(&acc[320 + lane + 32], a2hi * a2hi);
    }
    __syncthreads();
    for (int i = tid; i < 384; i += 256) atomicAdd(&g_stats[i], acc[i]);
}

// ---------------- K3: finalize BN coeffs ----------------
__global__ void k_fstats1(const float* __restrict__ gpos, const float* __restrict__ bepos,
                          const float* __restrict__ gfeat, const float* __restrict__ befeat,
                          const float* __restrict__ gsc1, const float* __restrict__ besc1,
                          const float* __restrict__ gsc2, const float* __restrict__ besc2) {
    int d = threadIdx.x;
    float n1 = (float)((size_t)NQ * KK);
    float s1, s2, g, be;
    if (d < 32) { s1 = g_stats[64 + d]; s2 = g_stats[96 + d]; g = gfeat[d]; be = befeat[d]; }
    else { int h = d - 32; s1 = g_stats[h]; s2 = g_stats[32 + h]; g = gpos[h]; be = bepos[h]; }
    float mu = s1 / n1, var = s2 / n1 - mu * mu;
    float a = g * rsqrtf(var + EPSV);
    g_bn[d] = a; g_bn[64 + d] = be - mu * a;

    float n2 = (float)NQ;
    s1 = g_stats[128 + d]; s2 = g_stats[192 + d];
    mu = s1 / n2; var = s2 / n2 - mu * mu;
    a = gsc1[d] * rsqrtf(var + EPSV);
    g_bn[128 + d] = a; g_bn[192 + d] = besc1[d] - mu * a;

    s1 = g_stats[256 + d]; s2 = g_stats[320 + d];
    mu = s1 / n2; var = s2 / n2 - mu * mu;
    a = gsc2[d] * rsqrtf(var + EPSV);
    g_bn[256 + d] = a; g_bn[320 + d] = besc2[d] - mu * a;
}

// ---------------- K4: attention + pooling + W_out + stats (FFMA2 score GEMM) ----------------
__global__ __launch_bounds__(256) void k_attn(const float* __restrict__ Ws,
                                              const float* __restrict__ Wo) {
    __shared__ __align__(16) float combT[8][DD][KKP];
    __shared__ float pool[8][DD];
    __shared__ float acc[128];
    int tid = threadIdx.x;
    if (tid < 128) acc[tid] = 0.f;
    __syncthreads();

    int warp = tid >> 5, lane = tid & 31;
    int q = blockIdx.x * 8 + warp;
    float a0 = g_bn[lane],      b0 = g_bn[64 + lane];
    float a1 = g_bn[lane + 32], b1 = g_bn[64 + lane + 32];
    const float* cp = g_comb + (size_t)q * KK * DD;

#pragma unroll
    for (int k = 0; k < KK; k++) {
        float v0 = fmaxf(fmaf(a0, cp[k * DD + lane],      b0), 0.f);
        float v1 = fmaxf(fmaf(a1, cp[k * DD + lane + 32], b1), 0.f);
        combT[warp][lane][k]      = v0;
        combT[warp][lane + 32][k] = v1;
    }
    __syncwarp();

    unsigned long long s0p[8], s1p[8];
#pragma unroll
    for (int j = 0; j < 8; j++) { s0p[j] = 0ull; s1p[j] = 0ull; }
    for (int dp = 0; dp < DD; dp++) {
        const float4* row = reinterpret_cast<const float4*>(combT[warp][dp]);
        float4 A0 = row[0], A1 = row[1], A2 = row[2], A3 = row[3];
        float w0 = Ws[dp * DD + lane];
        float w1 = Ws[dp * DD + lane + 32];
        unsigned long long w00 = pack2(w0, w0);
        unsigned long long w11 = pack2(w1, w1);
        unsigned long long ap[8];
        ap[0] = pack2(A0.x, A0.y); ap[1] = pack2(A0.z, A0.w);
        ap[2] = pack2(A1.x, A1.y); ap[3] = pack2(A1.z, A1.w);
        ap[4] = pack2(A2.x, A2.y); ap[5] = pack2(A2.z, A2.w);
        ap[6] = pack2(A3.x, A3.y); ap[7] = pack2(A3.z, A3.w);
#pragma unroll
        for (int j = 0; j < 8; j++) {
            ffma2(s0p[j], ap[j], w00);
            ffma2(s1p[j], ap[j], w11);
        }
    }
    float s0[KK], s1v[KK];
#pragma unroll
    for (int j = 0; j < 8; j++) {
        unpack2(s0p[j], s0[2 * j], s0[2 * j + 1]);
        unpack2(s1p[j], s1v[2 * j], s1v[2 * j + 1]);
    }

    float p0 = 0.f, p1 = 0.f;
    {
        float mx = s0[0];
#pragma unroll
        for (int k = 1; k < KK; k++) mx = fmaxf(mx, s0[k]);
        float sum = 0.f;
#pragma unroll
        for (int k = 0; k < KK; k++) { float e = __expf(s0[k] - mx); s0[k] = e; sum += e; }
        float inv = 1.f / sum;
        const float4* r0 = reinterpret_cast<const float4*>(combT[warp][lane]);
        float4 C0 = r0[0], C1 = r0[1], C2 = r0[2], C3 = r0[3];
        float cv[KK] = {C0.x, C0.y, C0.z, C0.w, C1.x, C1.y, C1.z, C1.w,
                        C2.x, C2.y, C2.z, C2.w, C3.x, C3.y, C3.z, C3.w};
#pragma unroll
        for (int k = 0; k < KK; k++) p0 = fmaf(s0[k] * inv, cv[k], p0);
    }
    {
        float mx = s1v[0];
#pragma unroll
        for (int k = 1; k < KK; k++) mx = fmaxf(mx, s1v[k]);
        float sum = 0.f;
#pragma unroll
        for (int k = 0; k < KK; k++) { float e = __expf(s1v[k] - mx); s1v[k] = e; sum += e; }
        float inv = 1.f / sum;
        const float4* r1 = reinterpret_cast<const float4*>(combT[warp][lane + 32]);
        float4 C0 = r1[0], C1 = r1[1], C2 = r1[2], C3 = r1[3];
        float cv[KK] = {C0.x, C0.y, C0.z, C0.w, C1.x, C1.y, C1.z, C1.w,
                        C2.x, C2.y, C2.z, C2.w, C3.x, C3.y, C3.z, C3.w};
#pragma unroll
        for (int k = 0; k < KK; k++) p1 = fmaf(s1v[k] * inv, cv[k], p1);
    }
    pool[warp][lane] = p0;
    pool[warp][lane + 32] = p1;
    __syncwarp();

    float o0 = 0.f, o1 = 0.f;
    for (int dp = 0; dp < DD; dp++) {
        float pv = pool[warp][dp];
        o0 = fmaf(pv, Wo[dp * DD + lane],      o0);
        o1 = fmaf(pv, Wo[dp * DD + lane + 32], o1);
    }
    g_outp[q * DD + lane] = o0;
    g_outp[q * DD + lane + 32] = o1;
    atomicAdd(&acc[lane], o0);
    atomicAdd(&acc[lane + 32], o1);
    atomicAdd(&acc[64 + lane], o0 * o0);
    atomicAdd(&acc[64 + lane + 32], o1 * o1);
    __syncthreads();
    if (tid < 128) atomicAdd(&g_stats[384 + tid], acc[tid]);
}

// ---------------- K5a: finalize out BN ----------------
__global__ void k_fout(const float* __restrict__ gout, const float* __restrict__ beout) {
    int d = threadIdx.x;
    float n = (float)NQ;
    float s1 = g_stats[384 + d], s2 = g_stats[448 + d];
    float mu = s1 / n, var = s2 / n - mu * mu;
    float a = gout[d] * rsqrtf(var + EPSV);
    g_bn[384 + d] = a; g_bn[448 + d] = beout[d] - mu * a;
}

// ---------------- K5: fused epilogue (coalesced), y transposed [B,D,M] ----------------
__global__ __launch_bounds__(256) void k_final(float* __restrict__ out) {
    __shared__ float sm[32][65];
    int blk = blockIdx.x;
    int b = blk >> 7;
    int m0 = (blk & 127) * 32;
    int warp = threadIdx.x >> 5, lane = threadIdx.x & 31;
#pragma unroll
    for (int i = 0; i < 4; i++) {
        int r = warp * 4 + i;
        int q = b * MM + m0 + r;
#pragma unroll
        for (int h = 0; h < 2; h++) {
            int d = lane + 32 * h;
            float o  = fmaxf(fmaf(g_bn[384 + d], g_outp[q * DD + d], g_bn[448 + d]), 0.f);
            float v1 = fmaf(g_bn[128 + d], g_sc1[q * DD + d], g_bn[192 + d]);
            float v2 = fmaf(g_bn[256 + d], g_sc2[q * DD + d], g_bn[320 + d]);
            sm[r][d] = fmaxf(o + v1 + v2, 0.f);
        }
    }
    __syncthreads();
#pragma unroll
    for (int i = 0; i < 8; i++) {
        int d = warp * 8 + i;
        out[24576 + ((size_t)(b * DD + d)) * MM + m0 + lane] = sm[lane][d];
    }
}

// ---------------- launch ----------------
extern "C" void kernel_launch(void* const* d_in, const int* in_sizes, int n_in,
                              void* d_out, int out_size) {
    const float* xyz    = (const float*)d_in[0];
    const float* feats  = (const float*)d_in[1];
    const int*   sidx   = (const int*)  d_in[2];
    const float* Wpos   = (const float*)d_in[3];
    const float* bpos   = (const float*)d_in[4];
    const float* gpos   = (const float*)d_in[5];
    const float* bepos  = (const float*)d_in[6];
    const float* Wfeat  = (const float*)d_in[7];
    const float* bfeat  = (const float*)d_in[8];
    const float* gfeat  = (const float*)d_in[9];
    const float* befeat = (const float*)d_in[10];
    const float* Wscore = (const float*)d_in[11];
    const float* Wout   = (const float*)d_in[12];
    const float* gout   = (const float*)d_in[13];
    const float* beout  = (const float*)d_in[14];
    const float* Wsc1   = (const float*)d_in[15];
    const float* gsc1   = (const float*)d_in[16];
    const float* besc1  = (const float*)d_in[17];
    const float* Wsc2   = (const float*)d_in[18];
    const float* gsc2   = (const float*)d_in[19];
    const float* besc2  = (const float*)d_in[20];
    float* out = (float*)d_out;

    k_init<<<(BB * NN) / 256, 256>>>(xyz, sidx, out);
    dim3 tb(32, 8);
    k_transpose<<<dim3(NN / 32, BB), tb>>>(feats);
    k_knn<<<NQ / 16, 256>>>(sidx);
    k_stage2<<<NQ / 8, 256>>>(xyz, sidx, Wpos, bpos, Wfeat, bfeat, Wsc1, Wsc2);
    k_fstats1<<<1, 64>>>(gpos, bepos, gfeat, befeat, gsc1, besc1, gsc2, besc2);
    k_attn<<<NQ / 8, 256>>>(Wscore, Wout);
    k_fout<<<1, 64>>>(gout, beout);
    k_final<<<256, 256>>>(out);
}

// round 17
// speedup vs baseline: 1.0867x; 1.0014x over previous
#include <cuda_runtime.h>
#include <stdint.h>
#include <float.h>

#define BB 2
#define NN 16384
#define MM 4096
#define CC 32
#define DD 64
#define HH 32
#define KK 16
#define KKP 20   // padded k-stride for combT
#define EPSV 1e-5f
#define NQ (BB*MM)   // 8192

// ---------------- scratch ----------------
__device__ float4 g_xyz4[BB*NN];              // padded xyz; .w = |p|^2
__device__ float  g_featsT[BB*NN*CC];
__device__ int    g_knn[NQ*KK];
__device__ float  g_comb[(size_t)NQ*KK*DD];
__device__ float  g_sc1[NQ*DD];
__device__ float  g_sc2[NQ*DD];
__device__ float  g_outp[NQ*DD];
__device__ float  g_stats[512];
__device__ float  g_bn[512];

// ---------------- f32x2 helpers (attn only) ----------------
__device__ __forceinline__ unsigned long long pack2(float lo, float hi) {
    unsigned long long r;
    asm("mov.b64 %0, {%1, %2};" : "=l"(r) : "f"(lo), "f"(hi));
    return r;
}
__device__ __forceinline__ void unpack2(unsigned long long v, float& lo, float& hi) {
    asm("mov.b64 {%0, %1}, %2;" : "=f"(lo), "=f"(hi) : "l"(v));
}
__device__ __forceinline__ void ffma2(unsigned long long& acc, unsigned long long a,
                                      unsigned long long b) {
    asm("fma.rn.f32x2 %0, %1, %2, %0;" : "+l"(acc) : "l"(a), "l"(b));
}

// ---------------- K0: zero stats, write xyz_ds + sample_idx, pad xyz ----------------
__global__ void k_init(const float* __restrict__ xyz, const int* __restrict__ sidx,
                       float* __restrict__ out) {
    int t = blockIdx.x * 256 + threadIdx.x;   // 32768 threads
    if (t < 512) g_stats[t] = 0.f;
    if (t < NQ) {
        int b = t >> 12;
        int n = sidx[t];
        const float* p = xyz + ((size_t)b * NN + n) * 3;
        out[t * 3 + 0] = p[0];
        out[t * 3 + 1] = p[1];
        out[t * 3 + 2] = p[2];
        out[24576 + 524288 + t] = (float)n;
    }
    if (t < BB * NN) {
        float x = xyz[3 * t], y = xyz[3 * t + 1], z = xyz[3 * t + 2];
        float w = fmaf(x, x, fmaf(y, y, z * z));
        g_xyz4[t] = make_float4(x, y, z, w);
    }
}

// ---------------- K0b: transpose feats [B,C,N] -> [B,N,C] (4 rows/thread) ----------------
__global__ void k_transpose(const float* __restrict__ feats) {
    __shared__ float tile[32][33];
    int b = blockIdx.y;
    int n0 = blockIdx.x * 32;
    int tx = threadIdx.x, ty = threadIdx.y;     // (32, 8)
#pragma unroll
    for (int i = 0; i < 4; i++) {
        int c = ty * 4 + i;
        tile[c][tx] = feats[((size_t)b * CC + c) * NN + n0 + tx];
    }
    __syncthreads();
#pragma unroll
    for (int i = 0; i < 4; i++) {
        int n = ty * 4 + i;
        g_featsT[((size_t)b * NN + n0 + n) * CC + tx] = tile[tx][n];
    }
}

// warp-shared sorted top-16 insert (lanes 0..15 ascending; lane 15 = threshold)
__device__ __forceinline__ void knn_insert(float nd, int ni, int lane,
                                           float& bk, int& bi, float& w) {
    float upk = __shfl_up_sync(0xffffffffu, bk, 1);
    int   upi = __shfl_up_sync(0xffffffffu, bi, 1);
    unsigned gt = __ballot_sync(0xffffffffu, (lane < KK) && (bk > nd));
    int fg = __ffs(gt) - 1;
    if ((lane < KK) && bk > nd) {
        if (lane == fg) { bk = nd;  bi = ni; }
        else            { bk = upk; bi = upi; }
    }
    w = __shfl_sync(0xffffffffu, bk, KK - 1);
}

// ---------------- K1: KNN — 2 queries/warp, 4-group batched ballots (measured optimum) ----------------
#define TS 2048
__global__ __launch_bounds__(256) void k_knn(const int* __restrict__ sidx) {
    __shared__ float4 tile[TS];
    int warp = threadIdx.x >> 5, lane = threadIdx.x & 31;
    int qbase = (blockIdx.x * 8 + warp) * 2;     // grid=512 -> queries 0..8191
    int b = qbase >> 12;
    const float4* xb = g_xyz4 + (size_t)b * NN;

    float4 q0p = xb[sidx[qbase]];
    float4 q1p = xb[sidx[qbase + 1]];
    float ax0 = -2.f * q0p.x, ay0 = -2.f * q0p.y, az0 = -2.f * q0p.z;
    float ax1 = -2.f * q1p.x, ay1 = -2.f * q1p.y, az1 = -2.f * q1p.z;

    float bk0 = FLT_MAX, bk1 = FLT_MAX;
    int   bi0 = 0,       bi1 = 0;
    float w0 = FLT_MAX,  w1 = FLT_MAX;

    for (int t0 = 0; t0 < NN; t0 += TS) {
        __syncthreads();
        for (int i = threadIdx.x; i < TS; i += 256)
            tile[i] = xb[t0 + i];
        __syncthreads();
        for (int i0 = 0; i0 < TS; i0 += 128) {
            float4 pa = tile[i0 + lane];
            float4 pb = tile[i0 + 32 + lane];
            float4 pc = tile[i0 + 64 + lane];
            float4 pd = tile[i0 + 96 + lane];
            float d00 = fmaf(pa.x, ax0, fmaf(pa.y, ay0, fmaf(pa.z, az0, pa.w)));
            float d01 = fmaf(pb.x, ax0, fmaf(pb.y, ay0, fmaf(pb.z, az0, pb.w)));
            float d02 = fmaf(pc.x, ax0, fmaf(pc.y, ay0, fmaf(pc.z, az0, pc.w)));
            float d03 = fmaf(pd.x, ax0, fmaf(pd.y, ay0, fmaf(pd.z, az0, pd.w)));
            float d10 = fmaf(pa.x, ax1, fmaf(pa.y, ay1, fmaf(pa.z, az1, pa.w)));
            float d11 = fmaf(pb.x, ax1, fmaf(pb.y, ay1, fmaf(pb.z, az1, pb.w)));
            float d12 = fmaf(pc.x, ax1, fmaf(pc.y, ay1, fmaf(pc.z, az1, pc.w)));
            float d13 = fmaf(pd.x, ax1, fmaf(pd.y, ay1, fmaf(pd.z, az1, pd.w)));
            float m0 = fminf(fminf(d00, d01), fminf(d02, d03));
            float m1 = fminf(fminf(d10, d11), fminf(d12, d13));
            unsigned ball0 = __ballot_sync(0xffffffffu, m0 < w0);
            while (ball0) {
                int src = __ffs(ball0) - 1;
                ball0 &= ball0 - 1;
                float nd;
                nd = __shfl_sync(0xffffffffu, d00, src);
                if (nd < w0) knn_insert(nd, t0 + i0 + src,      lane, bk0, bi0, w0);
                nd = __shfl_sync(0xffffffffu, d01, src);
                if (nd < w0) knn_insert(nd, t0 + i0 + 32 + src, lane, bk0, bi0, w0);
                nd = __shfl_sync(0xffffffffu, d02, src);
                if (nd < w0) knn_insert(nd, t0 + i0 + 64 + src, lane, bk0, bi0, w0);
                nd = __shfl_sync(0xffffffffu, d03, src);
                if (nd < w0) knn_insert(nd, t0 + i0 + 96 + src, lane, bk0, bi0, w0);
            }
            unsigned ball1 = __ballot_sync(0xffffffffu, m1 < w1);
            while (ball1) {
                int src = __ffs(ball1) - 1;
                ball1 &= ball1 - 1;
                float nd;
                nd = __shfl_sync(0xffffffffu, d10, src);
                if (nd < w1) knn_insert(nd, t0 + i0 + src,      lane, bk1, bi1, w1);
                nd = __shfl_sync(0xffffffffu, d11, src);
                if (nd < w1) knn_insert(nd, t0 + i0 + 32 + src, lane, bk1, bi1, w1);
                nd = __shfl_sync(0xffffffffu, d12, src);
                if (nd < w1) knn_insert(nd, t0 + i0 + 64 + src, lane, bk1, bi1, w1);
                nd = __shfl_sync(0xffffffffu, d13, src);
                if (nd < w1) knn_insert(nd, t0 + i0 + 96 + src, lane, bk1, bi1, w1);
            }
        }
    }
    if (lane < KK) {
        g_knn[qbase * KK + lane] = bi0;
        g_knn[(qbase + 1) * KK + lane] = bi1;
    }
}

// ---------------- K2: gather + pos/feat linear + shortcuts + stats (R13 scalar form) ----------------
__global__ __launch_bounds__(256) void k_stage2(
    const float* __restrict__ xyz, const int* __restrict__ sidx,
    const float* __restrict__ Wp, const float* __restrict__ bp,
    const float* __restrict__ Wf, const float* __restrict__ bf,
    const float* __restrict__ Wsc1, const float* __restrict__ Wsc2) {
    __shared__ __align__(16) float nf[8][KK][CC];
    __shared__ float posf[8][KK][10];
    __shared__ float mf[8][CC];
    __shared__ float cfs[8][CC];
    __shared__ int   nidx[8][KK];
    __shared__ float acc[384];
    __shared__ float swf[CC][HH];
    __shared__ float ssc1[CC][DD];
    __shared__ float ssc2[CC][DD];

    int tid = threadIdx.x;
    for (int i = tid; i < 384; i += 256) acc[i] = 0.f;
    for (int i = tid; i < CC * HH; i += 256) ((float*)swf)[i] = Wf[i];
    for (int i = tid; i < CC * DD; i += 256) {
        ((float*)ssc1)[i] = Wsc1[i];
        ((float*)ssc2)[i] = Wsc2[i];
    }
    __syncthreads();

    int warp = tid >> 5, lane = tid & 31;
    int q = blockIdx.x * 8 + warp;
    int b = q >> 12;
    const float* ftb = g_featsT + (size_t)b * NN * CC;
    const float4* xb = g_xyz4 + (size_t)b * NN;
    int sn = sidx[q];
    float4 qp = xb[sn];
    float qx = qp.x, qy = qp.y, qz = qp.z;

    if (lane < KK) nidx[warp][lane] = g_knn[q * KK + lane];
    __syncwarp();
#pragma unroll
    for (int k = 0; k < KK; k++) {
        int n = nidx[warp][k];
        nf[warp][k][lane] = ftb[n * CC + lane];
    }
    if (lane < KK) {
        int n = nidx[warp][lane];
        float4 pp = xb[n];
        float rx = qx - pp.x, ry = qy - pp.y, rz = qz - pp.z;
        float dist = sqrtf(rx * rx + ry * ry + rz * rz);
        float* pf = posf[warp][lane];
        pf[0] = qx; pf[1] = qy; pf[2] = qz;
        pf[3] = pp.x; pf[4] = pp.y; pf[5] = pp.z;
        pf[6] = rx; pf[7] = ry; pf[8] = rz; pf[9] = dist;
    }
    cfs[warp][lane] = ftb[sn * CC + lane];
    __syncwarp();

    float* cb = g_comb + (size_t)q * KK * DD;

    {
        float wp[10];
#pragma unroll
        for (int j = 0; j < 10; j++) wp[j] = Wp[j * HH + lane];
        float bias = bp[lane];
        float s1 = 0.f, s2 = 0.f;
        for (int k = 0; k < KK; k++) {
            float v0 = 0.f, v1 = 0.f;
#pragma unroll
            for (int j = 0; j < 5; j++) {
                v0 = fmaf(posf[warp][k][j],     wp[j],     v0);
                v1 = fmaf(posf[warp][k][j + 5], wp[j + 5], v1);
            }
            float v = bias + (v0 + v1);
            cb[k * DD + 32 + lane] = v;
            s1 += v; s2 = fmaf(v, v, s2);
        }
        atomicAdd(&acc[0 + lane], s1);
        atomicAdd(&acc[32 + lane], s2);
    }
    {
        float v[KK];
        float bias = bf[lane];
#pragma unroll
        for (int k = 0; k < KK; k++) v[k] = bias;
#pragma unroll
        for (int ch = 0; ch < 4; ch++) {
            float wq0 = swf[ch * 8 + 0][lane], wq1 = swf[ch * 8 + 1][lane];
            float wq2 = swf[ch * 8 + 2][lane], wq3 = swf[ch * 8 + 3][lane];
            float wq4 = swf[ch * 8 + 4][lane], wq5 = swf[ch * 8 + 5][lane];
            float wq6 = swf[ch * 8 + 6][lane], wq7 = swf[ch * 8 + 7][lane];
#pragma unroll
            for (int k = 0; k < KK; k++) {
                const float4* n4 = reinterpret_cast<const float4*>(nf[warp][k]);
                float4 na = n4[ch * 2], nb = n4[ch * 2 + 1];
                float t0 = fmaf(na.x, wq0, fmaf(na.y, wq1, fmaf(na.z, wq2, na.w * wq3)));
                float t1 = fmaf(nb.x, wq4, fmaf(nb.y, wq5, fmaf(nb.z, wq6, nb.w * wq7)));
                v[k] += t0 + t1;
            }
        }
        float s1 = 0.f, s2 = 0.f;
#pragma unroll
        for (int k = 0; k < KK; k++) {
            cb[k * DD + lane] = v[k];
            s1 += v[k]; s2 = fmaf(v[k], v[k], s2);
        }
        atomicAdd(&acc[64 + lane], s1);
        atomicAdd(&acc[96 + lane], s2);
    }
    {
        float mv = 0.f;
#pragma unroll
        for (int k = 0; k < KK; k++) mv += nf[warp][k][lane];
        mf[warp][lane] = mv * (1.f / 16.f);
    }
    __syncwarp();
    {
        float a1a = 0.f, a1b = 0.f, a1c = 0.f, a1d = 0.f;
        float a2a = 0.f, a2b = 0.f, a2c = 0.f, a2d = 0.f;
#pragma unroll
        for (int c = 0; c < CC; c += 2) {
            float m0 = mf[warp][c],  m1 = mf[warp][c + 1];
            float f0 = cfs[warp][c], f1 = cfs[warp][c + 1];
            a1a = fmaf(m0, ssc1[c][lane],          a1a);
            a1b = fmaf(m1, ssc1[c + 1][lane],      a1b);
            a1c = fmaf(m0, ssc1[c][lane + 32],     a1c);
            a1d = fmaf(m1, ssc1[c + 1][lane + 32], a1d);
            a2a = fmaf(f0, ssc2[c][lane],          a2a);
            a2b = fmaf(f1, ssc2[c + 1][lane],      a2b);
            a2c = fmaf(f0, ssc2[c][lane + 32],     a2c);
            a2d = fmaf(f1, ssc2[c + 1][lane + 32], a2d);
        }
        float a1lo = a1a + a1b, a1hi = a1c + a1d;
        float a2lo = a2a + a2b, a2hi = a2c + a2d;
        g_sc1[q * DD + lane] = a1lo;       g_sc1[q * DD + lane + 32] = a1hi;
        g_sc2[q * DD + lane] = a2lo;       g_sc2[q * DD + lane + 32] = a2hi;
        atomicAdd(&acc[128 + lane], a1lo);        atomicAdd(&acc[128 + lane + 32], a1hi);
        atomicAdd(&acc[192 + lane], a1lo * a1lo); atomicAdd(&acc[192 + lane + 32], a1hi * a1hi);
        atomicAdd(&acc[256 + lane], a2lo);        atomicAdd(&acc[256 + lane + 32], a2hi);
        atomicAdd(&acc[320 + lane], a2lo * a2lo); atomicAdd(&acc[320 + lane + 32], a2hi * a2hi);
    }
    __syncthreads();
    for (int i = tid; i < 384; i += 256) atomicAdd(&g_stats[i], acc[i]);
}

// ---------------- K3: finalize BN coeffs ----------------
__global__ void k_fstats1(const float* __restrict__ gpos, const float* __restrict__ bepos,
                          const float* __restrict__ gfeat, const float* __restrict__ befeat,
                          const float* __restrict__ gsc1, const float* __restrict__ besc1,
                          const float* __restrict__ gsc2, const float* __restrict__ besc2) {
    int d = threadIdx.x;
    float n1 = (float)((size_t)NQ * KK);
    float s1, s2, g, be;
    if (d < 32) { s1 = g_stats[64 + d]; s2 = g_stats[96 + d]; g = gfeat[d]; be = befeat[d]; }
    else { int h = d - 32; s1 = g_stats[h]; s2 = g_stats[32 + h]; g = gpos[h]; be = bepos[h]; }
    float mu = s1 / n1, var = s2 / n1 - mu * mu;
    float a = g * rsqrtf(var + EPSV);
    g_bn[d] = a; g_bn[64 + d] = be - mu * a;

    float n2 = (float)NQ;
    s1 = g_stats[128 + d]; s2 = g_stats[192 + d];
    mu = s1 / n2; var = s2 / n2 - mu * mu;
    a = gsc1[d] * rsqrtf(var + EPSV);
    g_bn[128 + d] = a; g_bn[192 + d] = besc1[d] - mu * a;

    s1 = g_stats[256 + d]; s2 = g_stats[320 + d];
    mu = s1 / n2; var = s2 / n2 - mu * mu;
    a = gsc2[d] * rsqrtf(var + EPSV);
    g_bn[256 + d] = a; g_bn[320 + d] = besc2[d] - mu * a;
}

// ---------------- K4: attention + pooling + W_out + stats (FFMA2 score GEMM) ----------------
__global__ __launch_bounds__(256) void k_attn(const float* __restrict__ Ws,
                                              const float* __restrict__ Wo) {
    __shared__ __align__(16) float combT[8][DD][KKP];
    __shared__ float pool[8][DD];
    __shared__ float acc[128];
    int tid = threadIdx.x;
    if (tid < 128) acc[tid] = 0.f;
    __syncthreads();

    int warp = tid >> 5, lane = tid & 31;
    int q = blockIdx.x * 8 + warp;
    float a0 = g_bn[lane],      b0 = g_bn[64 + lane];
    float a1 = g_bn[lane + 32], b1 = g_bn[64 + lane + 32];
    const float* cp = g_comb + (size_t)q * KK * DD;

#pragma unroll
    for (int k = 0; k < KK; k++) {
        float v0 = fmaxf(fmaf(a0, cp[k * DD + lane],      b0), 0.f);
        float v1 = fmaxf(fmaf(a1, cp[k * DD + lane + 32], b1), 0.f);
        combT[warp][lane][k]      = v0;
        combT[warp][lane + 32][k] = v1;
    }
    __syncwarp();

    unsigned long long s0p[8], s1p[8];
#pragma unroll
    for (int j = 0; j < 8; j++) { s0p[j] = 0ull; s1p[j] = 0ull; }
    for (int dp = 0; dp < DD; dp++) {
        const float4* row = reinterpret_cast<const float4*>(combT[warp][dp]);
        float4 A0 = row[0], A1 = row[1], A2 = row[2], A3 = row[3];
        float w0 = Ws[dp * DD + lane];
        float w1 = Ws[dp * DD + lane + 32];
        unsigned long long w00 = pack2(w0, w0);
        unsigned long long w11 = pack2(w1, w1);
        unsigned long long ap[8];
        ap[0] = pack2(A0.x, A0.y); ap[1] = pack2(A0.z, A0.w);
        ap[2] = pack2(A1.x, A1.y); ap[3] = pack2(A1.z, A1.w);
        ap[4] = pack2(A2.x, A2.y); ap[5] = pack2(A2.z, A2.w);
        ap[6] = pack2(A3.x, A3.y); ap[7] = pack2(A3.z, A3.w);
#pragma unroll
        for (int j = 0; j < 8; j++) {
            ffma2(s0p[j], ap[j], w00);
            ffma2(s1p[j], ap[j], w11);
        }
    }
    float s0[KK], s1v[KK];
#pragma unroll
    for (int j = 0; j < 8; j++) {
        unpack2(s0p[j], s0[2 * j], s0[2 * j + 1]);
        unpack2(s1p[j], s1v[2 * j], s1v[2 * j + 1]);
    }

    float p0 = 0.f, p1 = 0.f;
    {
        float mx = s0[0];
#pragma unroll
        for (int k = 1; k < KK; k++) mx = fmaxf(mx, s0[k]);
        float sum = 0.f;
#pragma unroll
        for (int k = 0; k < KK; k++) { float e = __expf(s0[k] - mx); s0[k] = e; sum += e; }
        float inv = 1.f / sum;
        const float4* r0 = reinterpret_cast<const float4*>(combT[warp][lane]);
        float4 C0 = r0[0], C1 = r0[1], C2 = r0[2], C3 = r0[3];
        float cv[KK] = {C0.x, C0.y, C0.z, C0.w, C1.x, C1.y, C1.z, C1.w,
                        C2.x, C2.y, C2.z, C2.w, C3.x, C3.y, C3.z, C3.w};
#pragma unroll
        for (int k = 0; k < KK; k++) p0 = fmaf(s0[k] * inv, cv[k], p0);
    }
    {
        float mx = s1v[0];
#pragma unroll
        for (int k = 1; k < KK; k++) mx = fmaxf(mx, s1v[k]);
        float sum = 0.f;
#pragma unroll
        for (int k = 0; k < KK; k++) { float e = __expf(s1v[k] - mx); s1v[k] = e; sum += e; }
        float inv = 1.f / sum;
        const float4* r1 = reinterpret_cast<const float4*>(combT[warp][lane + 32]);
        float4 C0 = r1[0], C1 = r1[1], C2 = r1[2], C3 = r1[3];
        float cv[KK] = {C0.x, C0.y, C0.z, C0.w, C1.x, C1.y, C1.z, C1.w,
                        C2.x, C2.y, C2.z, C2.w, C3.x, C3.y, C3.z, C3.w};
#pragma unroll
        for (int k = 0; k < KK; k++) p1 = fmaf(s1v[k] * inv, cv[k], p1);
    }
    pool[warp][lane] = p0;
    pool[warp][lane + 32] = p1;
    __syncwarp();

    float o0 = 0.f, o1 = 0.f;
    for (int dp = 0; dp < DD; dp++) {
        float pv = pool[warp][dp];
        o0 = fmaf(pv, Wo[dp * DD + lane],      o0);
        o1 = fmaf(pv, Wo[dp * DD + lane + 32], o1);
    }
    g_outp[q * DD + lane] = o0;
    g_outp[q * DD + lane + 32] = o1;
    atomicAdd(&acc[lane], o0);
    atomicAdd(&acc[lane + 32], o1);
    atomicAdd(&acc[64 + lane], o0 * o0);
    atomicAdd(&acc[64 + lane + 32], o1 * o1);
    __syncthreads();
    if (tid < 128) atomicAdd(&g_stats[384 + tid], acc[tid]);
}

// ---------------- K5a: finalize out BN ----------------
__global__ void k_fout(const float* __restrict__ gout, const float* __restrict__ beout) {
    int d = threadIdx.x;
    float n = (float)NQ;
    float s1 = g_stats[384 + d], s2 = g_stats[448 + d];
    float mu = s1 / n, var = s2 / n - mu * mu;
    float a = gout[d] * rsqrtf(var + EPSV);
    g_bn[384 + d] = a; g_bn[448 + d] = beout[d] - mu * a;
}

// ---------------- K5: fused epilogue (coalesced), y transposed [B,D,M] ----------------
__global__ __launch_bounds__(256) void k_final(float* __restrict__ out) {
    __shared__ float sm[32][65];
    int blk = blockIdx.x;
    int b = blk >> 7;
    int m0 = (blk & 127) * 32;
    int warp = threadIdx.x >> 5, lane = threadIdx.x & 31;
#pragma unroll
    for (int i = 0; i < 4; i++) {
        int r = warp * 4 + i;
        int q = b * MM + m0 + r;
#pragma unroll
        for (int h = 0; h < 2; h++) {
            int d = lane + 32 * h;
            float o  = fmaxf(fmaf(g_bn[384 + d], g_outp[q * DD + d], g_bn[448 + d]), 0.f);
            float v1 = fmaf(g_bn[128 + d], g_sc1[q * DD + d], g_bn[192 + d]);
            float v2 = fmaf(g_bn[256 + d], g_sc2[q * DD + d], g_bn[320 + d]);
            sm[r][d] = fmaxf(o + v1 + v2, 0.f);
        }
    }
    __syncthreads();
#pragma unroll
    for (int i = 0; i < 8; i++) {
        int d = warp * 8 + i;
        out[24576 + ((size_t)(b * DD + d)) * MM + m0 + lane] = sm[lane][d];
    }
}

// ---------------- launch ----------------
extern "C" void kernel_launch(void* const* d_in, const int* in_sizes, int n_in,
                              void* d_out, int out_size) {
    const float* xyz    = (const float*)d_in[0];
    const float* feats  = (const float*)d_in[1];
    const int*   sidx   = (const int*)  d_in[2];
    const float* Wpos   = (const float*)d_in[3];
    const float* bpos   = (const float*)d_in[4];
    const float* gpos   = (const float*)d_in[5];
    const float* bepos  = (const float*)d_in[6];
    const float* Wfeat  = (const float*)d_in[7];
    const float* bfeat  = (const float*)d_in[8];
    const float* gfeat  = (const float*)d_in[9];
    const float* befeat = (const float*)d_in[10];
    const float* Wscore = (const float*)d_in[11];
    const float* Wout   = (const float*)d_in[12];
    const float* gout   = (const float*)d_in[13];
    const float* beout  = (const float*)d_in[14];
    const float* Wsc1   = (const float*)d_in[15];
    const float* gsc1   = (const float*)d_in[16];
    const float* besc1  = (const float*)d_in[17];
    const float* Wsc2   = (const float*)d_in[18];
    const float* gsc2   = (const float*)d_in[19];
    const float* besc2  = (const float*)d_in[20];
    float* out = (float*)d_out;

    k_init<<<(BB * NN) / 256, 256>>>(xyz, sidx, out);
    dim3 tb(32, 8);
    k_transpose<<<dim3(NN / 32, BB), tb>>>(feats);
    k_knn<<<NQ / 16, 256>>>(sidx);
    k_stage2<<<NQ / 8, 256>>>(xyz, sidx, Wpos, bpos, Wfeat, bfeat, Wsc1, Wsc2);
    k_fstats1<<<1, 64>>>(gpos, bepos, gfeat, befeat, gsc1, besc1, gsc2, besc2);
    k_attn<<<NQ / 8, 256>>>(Wscore, Wout);
    k_fout<<<1, 64>>>(gout, beout);
    k_final<<<256, 256>>>(out);
}